// round 1
// baseline (speedup 1.0000x reference)
#include <cuda_runtime.h>
#include <cstddef>

#define N_NODES 20000
#define N_EDGES 160000
#define MUL0 32
#define MUL1 16
#define NODE_DIM 80           // MUL0 + 3*MUL1
#define EDGE_FEAT 128
#define HIDDEN 128
#define W_NUMEL 2560
#define ETILE 64
#define NCHUNK 32             // columns per fc_w2 chunk (80 chunks total)

// constants
#define C0f   0.14433756729740643f   // sqrt(1/48)
#define C1f   0.21650635094610965f   // sqrt(3/64)
#define IS3f  0.5773502691896258f    // 1/sqrt(3)
#define IS6f  0.40824829046386296f   // 1/sqrt(6)
#define EPS_LN 1e-5f

// ---------------- scratch (global device arrays; no runtime alloc) ----------------
__device__ float g_h[(size_t)N_EDGES * HIDDEN];   // relu(edge_attr@W1+b1)  (~82 MB)
__device__ float g_seg[(size_t)N_NODES * NODE_DIM];
__device__ float g_cnt[N_NODES];

// ---------------- zero scratch ----------------
__global__ void zero_kernel() {
    int i = blockIdx.x * blockDim.x + threadIdx.x;
    int stride = gridDim.x * blockDim.x;
    for (int j = i; j < N_NODES * NODE_DIM; j += stride) g_seg[j] = 0.0f;
    for (int j = i; j < N_NODES; j += stride) g_cnt[j] = 0.0f;
}

// ---------------- GEMM1: h = relu(edge_attr @ fc_w1 + b1) ----------------
// CTA: 256 threads, 64 edges. fc_w1 (64KB) + A tile (32KB) in SMEM.
#define GEMM1_SMEM ((HIDDEN * HIDDEN + ETILE * EDGE_FEAT) * sizeof(float))

__global__ __launch_bounds__(256, 2)
void gemm1_kernel(const float* __restrict__ edge_attr,
                  const float* __restrict__ fc_w1,
                  const float* __restrict__ fc_b1) {
    extern __shared__ float sm[];
    float* Ws = sm;                    // [128][128] row = h', col = hidden
    float* As = sm + HIDDEN * HIDDEN;  // [64][128]

    const int tid = threadIdx.x;
    const int e0 = blockIdx.x * ETILE;

    for (int i = tid; i < HIDDEN * HIDDEN; i += 256) Ws[i] = fc_w1[i];
    for (int i = tid; i < ETILE * EDGE_FEAT; i += 256)
        As[i] = edge_attr[(size_t)e0 * EDGE_FEAT + i];
    __syncthreads();

    const int col = tid & 127;
    const int eg  = tid >> 7;   // 0 or 1 -> edges eg*32 .. +31

    float acc[32];
#pragma unroll
    for (int e = 0; e < 32; e++) acc[e] = 0.0f;

#pragma unroll 4
    for (int h4 = 0; h4 < EDGE_FEAT / 4; h4++) {
        const float w0 = Ws[(4 * h4 + 0) * HIDDEN + col];
        const float w1 = Ws[(4 * h4 + 1) * HIDDEN + col];
        const float w2 = Ws[(4 * h4 + 2) * HIDDEN + col];
        const float w3 = Ws[(4 * h4 + 3) * HIDDEN + col];
#pragma unroll
        for (int e = 0; e < 32; e++) {
            const float4 hv = *reinterpret_cast<const float4*>(
                &As[(eg * 32 + e) * EDGE_FEAT + 4 * h4]);
            acc[e] = fmaf(hv.x, w0, fmaf(hv.y, w1, fmaf(hv.z, w2, fmaf(hv.w, w3, acc[e]))));
        }
    }

    const float bias = fc_b1[col];
#pragma unroll
    for (int e = 0; e < 32; e++) {
        float v = acc[e] + bias;
        g_h[(size_t)(e0 + eg * 32 + e) * HIDDEN + col] = fmaxf(v, 0.0f);
    }
}

// ---------------- fused GEMM2 + tensor product + scatter ----------------
// SMEM layout (floats):
//  h_s   [64][128]   8192
//  B_s   [128][32]   4096
//  a0s   [64][32]    2048   c0*sh0*x0[u]                (block1 -> out0)
//  a1s   [64][16]    1024   c0*is3*sum_i x1[u,i]*sh1[i] (block2 -> out0)
//  b3s   [64][32]    2048   c1*is3*x0[u]                (block3 -> out1*sh1[k])
//  b4s   [64][48]    3072   c1*is3*sh0*x1[u,i]          (block4 -> out1)
//  b5s   [64][48]    3072   c1*is6*(x1[u] x sh1)[k]     (block5 -> out1)
//  sh1s  [64][3]      192
//  srcs  [64] ints     64
#define EDGE_SMEM_FLOATS (8192 + 4096 + 2048 + 1024 + 2048 + 3072 + 3072 + 192 + 64)
#define EDGE_SMEM (EDGE_SMEM_FLOATS * sizeof(float))

__global__ __launch_bounds__(256, 2)
void edge_kernel(const float* __restrict__ node_attr,
                 const float* __restrict__ edge_sh,
                 const float* __restrict__ fc_w2,
                 const float* __restrict__ fc_b2,
                 const int*   __restrict__ edge_index) {
    extern __shared__ float sm[];
    float* h_s  = sm;                     // 8192
    float* B_s  = h_s  + 64 * 128;        // 4096
    float* a0s  = B_s  + 128 * 32;        // 2048
    float* a1s  = a0s  + 64 * 32;         // 1024
    float* b3s  = a1s  + 64 * 16;         // 2048
    float* b4s  = b3s  + 64 * 32;         // 3072
    float* b5s  = b4s  + 64 * 48;         // 3072
    float* sh1s = b5s  + 64 * 48;         // 192
    int*   srcs = (int*)(sh1s + 64 * 3);  // 64

    const int tid = threadIdx.x;
    const int e0 = blockIdx.x * ETILE;

    // ---- gather & fold per-edge left vectors ----
    if (tid < ETILE) {
        const int eg  = e0 + tid;
        const int src = edge_index[eg];
        const int dst = edge_index[N_EDGES + eg];
        srcs[tid] = src;
        atomicAdd(&g_cnt[src], 1.0f);

        const float* na = node_attr + (size_t)dst * NODE_DIM;
        const float sh0 = edge_sh[(size_t)eg * 4 + 0];
        const float s1x = edge_sh[(size_t)eg * 4 + 1];
        const float s1y = edge_sh[(size_t)eg * 4 + 2];
        const float s1z = edge_sh[(size_t)eg * 4 + 3];
        sh1s[tid * 3 + 0] = s1x;
        sh1s[tid * 3 + 1] = s1y;
        sh1s[tid * 3 + 2] = s1z;

        const float k_a0 = C0f * sh0;
        const float k_a1 = C0f * IS3f;
        const float k_b3 = C1f * IS3f;
        const float k_b4 = C1f * IS3f * sh0;
        const float k_b5 = C1f * IS6f;

#pragma unroll
        for (int u = 0; u < MUL0; u++) {
            const float x0 = na[u];
            a0s[tid * 32 + u] = k_a0 * x0;
            b3s[tid * 32 + u] = k_b3 * x0;
        }
#pragma unroll
        for (int u = 0; u < MUL1; u++) {
            const float xx = na[32 + 3 * u + 0];
            const float xy = na[32 + 3 * u + 1];
            const float xz = na[32 + 3 * u + 2];
            a1s[tid * 16 + u] = k_a1 * (xx * s1x + xy * s1y + xz * s1z);
            b4s[tid * 48 + 3 * u + 0] = k_b4 * xx;
            b4s[tid * 48 + 3 * u + 1] = k_b4 * xy;
            b4s[tid * 48 + 3 * u + 2] = k_b4 * xz;
            // cross(x1[u], sh1)
            b5s[tid * 48 + 3 * u + 0] = k_b5 * (xy * s1z - xz * s1y);
            b5s[tid * 48 + 3 * u + 1] = k_b5 * (xz * s1x - xx * s1z);
            b5s[tid * 48 + 3 * u + 2] = k_b5 * (xx * s1y - xy * s1x);
        }
    }

    // ---- stage h tile ----
    for (int i = tid; i < ETILE * HIDDEN; i += 256)
        h_s[i] = g_h[(size_t)e0 * HIDDEN + i];

    const int c  = tid & 31;   // chunk-local column
    const int wp = tid >> 5;   // warp id -> 8 edges
    const int eb = wp * 8;

    float outA[8], t3r[8], t4r[8][3], t5r[8][3];
#pragma unroll
    for (int e = 0; e < 8; e++) {
        outA[e] = 0.0f; t3r[e] = 0.0f;
#pragma unroll
        for (int k = 0; k < 3; k++) { t4r[e][k] = 0.0f; t5r[e][k] = 0.0f; }
    }

    // ---- main loop: 80 chunks of 32 fc_w2 columns ----
    for (int j = 0; j < W_NUMEL / NCHUNK; j++) {
        __syncthreads();
        // load B chunk [128 h'][32 cols]
#pragma unroll
        for (int i = tid; i < HIDDEN * NCHUNK; i += 256) {
            const int hh = i >> 5, cc = i & 31;
            B_s[i] = fc_w2[(size_t)hh * W_NUMEL + j * NCHUNK + cc];
        }
        __syncthreads();

        const float bias = __ldg(&fc_b2[j * NCHUNK + c]);
        float acc[8];
#pragma unroll
        for (int e = 0; e < 8; e++) acc[e] = bias;

#pragma unroll 4
        for (int h4 = 0; h4 < HIDDEN / 4; h4++) {
            const float b0 = B_s[(4 * h4 + 0) * 32 + c];
            const float b1 = B_s[(4 * h4 + 1) * 32 + c];
            const float b2 = B_s[(4 * h4 + 2) * 32 + c];
            const float b3 = B_s[(4 * h4 + 3) * 32 + c];
#pragma unroll
            for (int e = 0; e < 8; e++) {
                const float4 hv = *reinterpret_cast<const float4*>(
                    &h_s[(eb + e) * HIDDEN + 4 * h4]);
                acc[e] = fmaf(hv.x, b0, fmaf(hv.y, b1, fmaf(hv.z, b2, fmaf(hv.w, b3, acc[e]))));
            }
        }

        // ---- epilogue contraction: chunk j -> (block, u) ----
        if (j < 32) {                       // block1: w1[u=j][w=c]
#pragma unroll
            for (int e = 0; e < 8; e++) outA[e] += a0s[(eb + e) * 32 + j] * acc[e];
        } else if (j < 48) {                // block2: w2[u=j-32][w=c]
            const int u = j - 32;
#pragma unroll
            for (int e = 0; e < 8; e++) outA[e] += a1s[(eb + e) * 16 + u] * acc[e];
        } else if (j < 64) {                // block3: w3[u][w=c%16]
            const int u = (j - 48) * 2 + (c >> 4);
#pragma unroll
            for (int e = 0; e < 8; e++) t3r[e] += b3s[(eb + e) * 32 + u] * acc[e];
        } else if (j < 72) {                // block4
            const int u = (j - 64) * 2 + (c >> 4);
#pragma unroll
            for (int e = 0; e < 8; e++)
#pragma unroll
                for (int k = 0; k < 3; k++)
                    t4r[e][k] += b4s[(eb + e) * 48 + 3 * u + k] * acc[e];
        } else {                            // block5
            const int u = (j - 72) * 2 + (c >> 4);
#pragma unroll
            for (int e = 0; e < 8; e++)
#pragma unroll
                for (int k = 0; k < 3; k++)
                    t5r[e][k] += b5s[(eb + e) * 48 + 3 * u + k] * acc[e];
        }
    }

    // ---- combine lane pairs (c, c^16) for the w<16 blocks, then scatter ----
    const unsigned full = 0xFFFFFFFFu;
#pragma unroll
    for (int e = 0; e < 8; e++) {
        const int src = srcs[eb + e];
        atomicAdd(&g_seg[(size_t)src * NODE_DIM + c], outA[e]);

        float t3f = t3r[e] + __shfl_xor_sync(full, t3r[e], 16);
        float t4f[3], t5f[3];
#pragma unroll
        for (int k = 0; k < 3; k++) {
            t4f[k] = t4r[e][k] + __shfl_xor_sync(full, t4r[e][k], 16);
            t5f[k] = t5r[e][k] + __shfl_xor_sync(full, t5r[e][k], 16);
        }
        if (c < 16) {
#pragma unroll
            for (int k = 0; k < 3; k++) {
                const float val = sh1s[(eb + e) * 3 + k] * t3f + t4f[k] + t5f[k];
                atomicAdd(&g_seg[(size_t)src * NODE_DIM + 32 + 3 * c + k], val);
            }
        }
    }
}

// ---------------- node epilogue: mean, residual, equivariant layernorm ----------------
__global__ void node_kernel(const float* __restrict__ node_attr,
                            const float* __restrict__ mean_shift,
                            const float* __restrict__ aw,
                            const float* __restrict__ ab,
                            float* __restrict__ out) {
    const int warp = (blockIdx.x * blockDim.x + threadIdx.x) >> 5;
    const int lane = threadIdx.x & 31;
    if (warp >= N_NODES) return;
    const unsigned full = 0xFFFFFFFFu;

    const float inv = 1.0f / fmaxf(g_cnt[warp], 1.0f);
    const float* seg = g_seg + (size_t)warp * NODE_DIM;
    const float* na  = node_attr + (size_t)warp * NODE_DIM;

    // scalar channel (32 values, one per lane)
    float o0 = seg[lane] * inv + na[lane];
    float m = o0;
#pragma unroll
    for (int off = 16; off; off >>= 1) m += __shfl_xor_sync(full, m, off);
    m *= (1.0f / 32.0f);
    const float f0 = o0 - m * mean_shift[lane];
    float s = f0 * f0;
#pragma unroll
    for (int off = 16; off; off >>= 1) s += __shfl_xor_sync(full, s, off);
    const float sc0 = rsqrtf(s * (1.0f / 32.0f) + EPS_LN) * aw[lane];
    out[(size_t)warp * NODE_DIM + lane] = f0 * sc0 + ab[lane];

    // vector channel (16 vectors of 3, lanes 0..15)
    float vx = 0.0f, vy = 0.0f, vz = 0.0f, msv = 0.0f;
    if (lane < 16) {
        vx = seg[32 + 3 * lane + 0] * inv + na[32 + 3 * lane + 0];
        vy = seg[32 + 3 * lane + 1] * inv + na[32 + 3 * lane + 1];
        vz = seg[32 + 3 * lane + 2] * inv + na[32 + 3 * lane + 2];
        msv = mean_shift[32 + lane];
    }
    float mx = vx, my = vy, mz = vz;
#pragma unroll
    for (int off = 16; off; off >>= 1) {
        mx += __shfl_xor_sync(full, mx, off);
        my += __shfl_xor_sync(full, my, off);
        mz += __shfl_xor_sync(full, mz, off);
    }
    mx *= (1.0f / 16.0f); my *= (1.0f / 16.0f); mz *= (1.0f / 16.0f);
    const float fx = vx - mx * msv;
    const float fy = vy - my * msv;
    const float fz = vz - mz * msv;
    float sq = (lane < 16) ? (fx * fx + fy * fy + fz * fz) : 0.0f;
#pragma unroll
    for (int off = 16; off; off >>= 1) sq += __shfl_xor_sync(full, sq, off);
    if (lane < 16) {
        const float sc1 = rsqrtf(sq * (1.0f / 48.0f) + EPS_LN) * aw[32 + lane];
        out[(size_t)warp * NODE_DIM + 32 + 3 * lane + 0] = fx * sc1;
        out[(size_t)warp * NODE_DIM + 32 + 3 * lane + 1] = fy * sc1;
        out[(size_t)warp * NODE_DIM + 32 + 3 * lane + 2] = fz * sc1;
    }
}

// ---------------- launch ----------------
extern "C" void kernel_launch(void* const* d_in, const int* in_sizes, int n_in,
                              void* d_out, int out_size) {
    const float* node_attr  = (const float*)d_in[0];
    const float* edge_attr  = (const float*)d_in[1];
    const float* edge_sh    = (const float*)d_in[2];
    const float* fc_w1      = (const float*)d_in[3];
    const float* fc_b1      = (const float*)d_in[4];
    const float* fc_w2      = (const float*)d_in[5];
    const float* fc_b2      = (const float*)d_in[6];
    const float* mean_shift = (const float*)d_in[7];
    const float* aw         = (const float*)d_in[8];
    const float* ab         = (const float*)d_in[9];
    const int*   edge_index = (const int*)d_in[10];
    float* out = (float*)d_out;

    cudaFuncSetAttribute(gemm1_kernel, cudaFuncAttributeMaxDynamicSharedMemorySize, (int)GEMM1_SMEM);
    cudaFuncSetAttribute(edge_kernel,  cudaFuncAttributeMaxDynamicSharedMemorySize, (int)EDGE_SMEM);

    zero_kernel<<<160, 256>>>();
    gemm1_kernel<<<N_EDGES / ETILE, 256, GEMM1_SMEM>>>(edge_attr, fc_w1, fc_b1);
    edge_kernel<<<N_EDGES / ETILE, 256, EDGE_SMEM>>>(node_attr, edge_sh, fc_w2, fc_b2, edge_index);
    node_kernel<<<(N_NODES * 32 + 255) / 256, 256>>>(node_attr, mean_shift, aw, ab, out);
}

// round 3
// speedup vs baseline: 3.7160x; 3.7160x over previous
#include <cuda_runtime.h>
#include <cuda_bf16.h>
#include <cstdint>
#include <cstddef>

#define N_NODES 20000
#define N_EDGES 160000
#define MUL0 32
#define MUL1 16
#define NODE_DIM 80
#define EDGE_FEAT 128
#define HIDDEN 128
#define W_NUMEL 2560
#define MTILE 128                     // edges per CTA
#define NTILES (N_EDGES / MTILE)      // 1250
#define TILE_ELEMS (MTILE * HIDDEN)   // 16384
#define NCHUNK 64                     // fc_w2 cols per chunk
#define NCHUNKS (W_NUMEL / NCHUNK)    // 40

#define C0f   0.14433756729740643f
#define C1f   0.21650635094610965f
#define IS3f  0.5773502691896258f
#define IS6f  0.40824829046386296f
#define C0IS3 (C0f * IS3f)
#define C1IS3 (C1f * IS3f)
#define C1IS6 (C1f * IS6f)
#define EPS_LN 1e-5f

// ---------------- device scratch ----------------
__device__ __align__(16) __nv_bfloat16 g_Ahi[(size_t)NTILES * TILE_ELEMS]; // [tile][m][k]
__device__ __align__(16) __nv_bfloat16 g_Alo[(size_t)NTILES * TILE_ELEMS];
__device__ __align__(16) __nv_bfloat16 g_Bhi[(size_t)W_NUMEL * HIDDEN];    // B^T: [n][k]
__device__ __align__(16) __nv_bfloat16 g_Blo[(size_t)W_NUMEL * HIDDEN];
__device__ float g_seg[(size_t)N_NODES * NODE_DIM];
__device__ float g_cnt[N_NODES];

// ---------------- PTX helpers ----------------
__device__ __forceinline__ uint32_t smem_u32(const void* p) {
    uint32_t a;
    asm("{ .reg .u64 t; cvta.to.shared.u64 t, %1; cvt.u32.u64 %0, t; }" : "=r"(a) : "l"(p));
    return a;
}
__device__ __forceinline__ void ldsm_x4(uint32_t* r, uint32_t addr) {
    asm volatile("ldmatrix.sync.aligned.m8n8.x4.shared.b16 {%0,%1,%2,%3}, [%4];"
        : "=r"(r[0]), "=r"(r[1]), "=r"(r[2]), "=r"(r[3]) : "r"(addr));
}
__device__ __forceinline__ void mma_bf16(float* c, const uint32_t* a, uint32_t b0, uint32_t b1) {
    asm volatile("mma.sync.aligned.m16n8k16.row.col.f32.bf16.bf16.f32 "
        "{%0,%1,%2,%3}, {%4,%5,%6,%7}, {%8,%9}, {%0,%1,%2,%3};"
        : "+f"(c[0]), "+f"(c[1]), "+f"(c[2]), "+f"(c[3])
        : "r"(a[0]), "r"(a[1]), "r"(a[2]), "r"(a[3]), "r"(b0), "r"(b1));
}
__device__ __forceinline__ void cp_async16(uint32_t smem_addr, const void* gptr) {
    asm volatile("cp.async.ca.shared.global [%0], [%1], 16;" :: "r"(smem_addr), "l"(gptr));
}
#define CP_COMMIT() asm volatile("cp.async.commit_group;" ::: "memory")
#define CP_WAIT_1() asm volatile("cp.async.wait_group 1;" ::: "memory")
#define CP_WAIT_0() asm volatile("cp.async.wait_group 0;" ::: "memory")

// ---------------- zero scratch ----------------
__global__ void zero_kernel() {
    int i = blockIdx.x * blockDim.x + threadIdx.x;
    int stride = gridDim.x * blockDim.x;
    for (int j = i; j < N_NODES * NODE_DIM; j += stride) g_seg[j] = 0.0f;
    for (int j = i; j < N_NODES; j += stride) g_cnt[j] = 0.0f;
}

// ---------------- B preprocess: fc_w2[k][n] -> B^T [n][k] bf16 hi/lo ----------------
__global__ void bprep_kernel(const float* __restrict__ fc_w2) {
    int idx = blockIdx.x * blockDim.x + threadIdx.x;
    int stride = gridDim.x * blockDim.x;
    for (int i = idx; i < HIDDEN * W_NUMEL; i += stride) {
        const int n = i / HIDDEN;
        const int k = i % HIDDEN;
        const float w = fc_w2[(size_t)k * W_NUMEL + n];
        const __nv_bfloat16 hi = __float2bfloat16(w);
        const __nv_bfloat16 lo = __float2bfloat16(w - __bfloat162float(hi));
        g_Bhi[i] = hi;
        g_Blo[i] = lo;
    }
}

// ---------------- GEMM1: h = relu(edge_attr @ fc_w1 + b1) -> bf16 hi/lo, row-major ----------------
#define GEMM1_SMEM ((HIDDEN * HIDDEN + MTILE * EDGE_FEAT) * sizeof(float))

__global__ __launch_bounds__(512, 1)
void gemm1_kernel(const float* __restrict__ edge_attr,
                  const float* __restrict__ fc_w1,
                  const float* __restrict__ fc_b1) {
    extern __shared__ float sm[];
    float* Ws = sm;
    float* As = sm + HIDDEN * HIDDEN;

    const int tid = threadIdx.x;
    const int e0 = blockIdx.x * MTILE;

    for (int i = tid; i < HIDDEN * HIDDEN; i += 512) Ws[i] = fc_w1[i];
    for (int i = tid; i < MTILE * EDGE_FEAT; i += 512)
        As[i] = edge_attr[(size_t)e0 * EDGE_FEAT + i];
    __syncthreads();

    const int col = tid & 127;
    const int eg  = tid >> 7;   // 0..3 -> 32 edges each

    float acc[32];
#pragma unroll
    for (int e = 0; e < 32; e++) acc[e] = 0.0f;

#pragma unroll 4
    for (int h4 = 0; h4 < EDGE_FEAT / 4; h4++) {
        const float w0 = Ws[(4 * h4 + 0) * HIDDEN + col];
        const float w1 = Ws[(4 * h4 + 1) * HIDDEN + col];
        const float w2 = Ws[(4 * h4 + 2) * HIDDEN + col];
        const float w3 = Ws[(4 * h4 + 3) * HIDDEN + col];
#pragma unroll
        for (int e = 0; e < 32; e++) {
            const float4 hv = *reinterpret_cast<const float4*>(&As[(eg * 32 + e) * EDGE_FEAT + 4 * h4]);
            acc[e] = fmaf(hv.x, w0, fmaf(hv.y, w1, fmaf(hv.z, w2, fmaf(hv.w, w3, acc[e]))));
        }
    }

    const float bias = fc_b1[col];
#pragma unroll
    for (int e = 0; e < 32; e++) {
        const int m = eg * 32 + e;
        const float v = fmaxf(acc[e] + bias, 0.0f);
        const __nv_bfloat16 hi = __float2bfloat16(v);
        const __nv_bfloat16 lo = __float2bfloat16(v - __bfloat162float(hi));
        g_Ahi[(size_t)blockIdx.x * TILE_ELEMS + m * HIDDEN + col] = hi;
        g_Alo[(size_t)blockIdx.x * TILE_ELEMS + m * HIDDEN + col] = lo;
    }
}

// ---------------- fused HMMA GEMM2 + tensor product + scatter ----------------
// SMEM (bytes):
//  A_hi  [128 rows][272]  34816   @ 0
//  A_lo  [128][272]       34816   @ 34816
//  B buf0 hi[64][272] lo[64][272] 34816 @ 69632
//  B buf1                 34816   @ 104448
//  b2s   2560 f           10240   @ 139264
//  x0s   [128][33] f      16896   @ 149504
//  x1s   [128][49] f      25088   @ 166400
//  shs   [128][4]  f       2048   @ 191488
//  srcs  [128] int          512   @ 193536
#define OFF_AHI 0
#define OFF_ALO 34816
#define OFF_B   69632
#define BBUF_STRIDE 34816
#define BLO_OFF 17408
#define OFF_B2  139264
#define OFF_X0  149504
#define OFF_X1  166400
#define OFF_SH  191488
#define OFF_SRC 193536
#define EDGE_SMEM 194048
#define ROWB 272

__global__ __launch_bounds__(256, 1)
void edge_kernel(const float* __restrict__ node_attr,
                 const float* __restrict__ edge_sh,
                 const float* __restrict__ fc_b2,
                 const int*   __restrict__ edge_index) {
    extern __shared__ char smc[];
    const uint32_t smb = smem_u32(smc);
    float* b2s = (float*)(smc + OFF_B2);
    float* x0s = (float*)(smc + OFF_X0);
    float* x1s = (float*)(smc + OFF_X1);
    float* shs = (float*)(smc + OFF_SH);
    int*  srcs = (int*)(smc + OFF_SRC);

    const int tid  = threadIdx.x;
    const int w    = tid >> 5;      // warp 0..7 -> rows 16w..16w+15
    const int lane = tid & 31;
    const int e0 = blockIdx.x * MTILE;

    // ---- issue B chunk 0 loads (cp.async) ----
    {
        const size_t gbase = 0;  // chunk 0: n rows 0..63
#pragma unroll
        for (int it = 0; it < 8; it++) {
            const int i = tid + it * 256;           // 0..2047
            const int part = i & 31;
            const int row  = i >> 5;                // 0..63
            const int hl   = part >> 4;             // 0 hi, 1 lo
            const int kc   = part & 15;             // 16B chunk
            const __nv_bfloat16* gp = (hl ? g_Blo : g_Bhi) + gbase + (size_t)row * HIDDEN + kc * 8;
            cp_async16(smb + OFF_B + hl * BLO_OFF + row * ROWB + kc * 16, gp);
        }
        CP_COMMIT();
    }

    // ---- stage A hi/lo into padded SMEM ----
    {
        const int4* gh = (const int4*)(g_Ahi + (size_t)blockIdx.x * TILE_ELEMS);
        const int4* gl = (const int4*)(g_Alo + (size_t)blockIdx.x * TILE_ELEMS);
#pragma unroll
        for (int it = 0; it < 8; it++) {
            const int i = tid + it * 256;           // 0..2047 : row(128) x kc(16)
            const int row = i >> 4;
            const int kc  = i & 15;
            *(int4*)(smc + OFF_AHI + row * ROWB + kc * 16) = gh[i];
            *(int4*)(smc + OFF_ALO + row * ROWB + kc * 16) = gl[i];
        }
    }
    for (int i = tid; i < W_NUMEL; i += 256) b2s[i] = fc_b2[i];

    // ---- gather per-edge vectors ----
    if (tid < MTILE) {
        const int eg  = e0 + tid;
        const int src = edge_index[eg];
        const int dst = edge_index[N_EDGES + eg];
        srcs[tid] = src;
        atomicAdd(&g_cnt[src], 1.0f);
        const float4* na = (const float4*)(node_attr + (size_t)dst * NODE_DIM);
#pragma unroll
        for (int q = 0; q < 8; q++) {
            const float4 v = na[q];
            x0s[tid * 33 + 4 * q + 0] = v.x;
            x0s[tid * 33 + 4 * q + 1] = v.y;
            x0s[tid * 33 + 4 * q + 2] = v.z;
            x0s[tid * 33 + 4 * q + 3] = v.w;
        }
#pragma unroll
        for (int q = 0; q < 12; q++) {
            const float4 v = na[8 + q];
            x1s[tid * 49 + 4 * q + 0] = v.x;
            x1s[tid * 49 + 4 * q + 1] = v.y;
            x1s[tid * 49 + 4 * q + 2] = v.z;
            x1s[tid * 49 + 4 * q + 3] = v.w;
        }
        const float4 sh4 = *(const float4*)(edge_sh + (size_t)eg * 4);
        shs[tid * 4 + 0] = sh4.x;
        shs[tid * 4 + 1] = sh4.y;
        shs[tid * 4 + 2] = sh4.z;
        shs[tid * 4 + 3] = sh4.w;
    }
    __syncthreads();

    // ---- per-thread row constants ----
    const int q2 = 2 * (lane & 3);          // 2q
    const int r8 = lane >> 2;               // 0..7
    const int mA = 16 * w + r8;             // row0; row1 = mA+8
    float sh0r[2], sh1r[2][3];
#pragma unroll
    for (int rr = 0; rr < 2; rr++) {
        const int mm = mA + 8 * rr;
        sh0r[rr] = shs[mm * 4 + 0];
        sh1r[rr][0] = shs[mm * 4 + 1];
        sh1r[rr][1] = shs[mm * 4 + 2];
        sh1r[rr][2] = shs[mm * 4 + 3];
    }

    // ldmatrix base addresses
    const uint32_t aRow = (uint32_t)(16 * w + (lane & 7) + ((lane >> 3) & 1) * 8);
    const uint32_t aKoff = (uint32_t)(((lane >> 4) & 1) * 16);
    const uint32_t aHiBase = smb + OFF_AHI + aRow * ROWB + aKoff;
    const uint32_t aLoBase = smb + OFF_ALO + aRow * ROWB + aKoff;
    const uint32_t bRow = (uint32_t)((lane & 7) + ((lane >> 4) & 1) * 8);
    const uint32_t bKoff = (uint32_t)(((lane >> 3) & 1) * 16);
    const uint32_t bBase0 = smb + OFF_B + bRow * ROWB + bKoff;

    // accumulators
    float accO[2][8], accT3[2][4], accV[2][4][3];
#pragma unroll
    for (int rr = 0; rr < 2; rr++) {
#pragma unroll
        for (int i = 0; i < 8; i++) accO[rr][i] = 0.0f;
#pragma unroll
        for (int i = 0; i < 4; i++) {
            accT3[rr][i] = 0.0f;
#pragma unroll
            for (int k = 0; k < 3; k++) accV[rr][i][k] = 0.0f;
        }
    }

    // ---- main loop over 40 N-chunks ----
    for (int j = 0; j < NCHUNKS; j++) {
        // issue next chunk loads
        if (j + 1 < NCHUNKS) {
            const size_t gbase = (size_t)(j + 1) * NCHUNK * HIDDEN;
            const uint32_t sb = smb + OFF_B + ((j + 1) & 1) * BBUF_STRIDE;
#pragma unroll
            for (int it = 0; it < 8; it++) {
                const int i = tid + it * 256;
                const int part = i & 31;
                const int row  = i >> 5;
                const int hl   = part >> 4;
                const int kc   = part & 15;
                const __nv_bfloat16* gp = (hl ? g_Blo : g_Bhi) + gbase + (size_t)row * HIDDEN + kc * 8;
                cp_async16(sb + hl * BLO_OFF + row * ROWB + kc * 16, gp);
            }
            CP_COMMIT();
            CP_WAIT_1();
        } else {
            CP_WAIT_0();
        }
        __syncthreads();

        const uint32_t bb = bBase0 + (j & 1) * BBUF_STRIDE;

        // ---- MMA: C[16 x 64] in regs, 3-pass split ----
        float c[8][4];
#pragma unroll
        for (int t = 0; t < 8; t++)
#pragma unroll
            for (int i = 0; i < 4; i++) c[t][i] = 0.0f;

#pragma unroll
        for (int ks = 0; ks < 8; ks++) {
            uint32_t ah[4], al[4];
            ldsm_x4(ah, aHiBase + ks * 32);
            ldsm_x4(al, aLoBase + ks * 32);
#pragma unroll
            for (int tp = 0; tp < 4; tp++) {
                uint32_t bh[4], bl[4];
                ldsm_x4(bh, bb + tp * (16 * ROWB) + ks * 32);
                ldsm_x4(bl, bb + BLO_OFF + tp * (16 * ROWB) + ks * 32);
                mma_bf16(c[2 * tp],     ah, bh[0], bh[1]);
                mma_bf16(c[2 * tp],     ah, bl[0], bl[1]);
                mma_bf16(c[2 * tp],     al, bh[0], bh[1]);
                mma_bf16(c[2 * tp + 1], ah, bh[2], bh[3]);
                mma_bf16(c[2 * tp + 1], ah, bl[2], bl[3]);
                mma_bf16(c[2 * tp + 1], al, bh[2], bh[3]);
            }
        }
        __syncthreads();   // B buffer consumed; safe for next-next load

        // ---- epilogue contraction (groups g = 2j, 2j+1) ----
        if (j < 16) {                               // block1 -> out0
            float s[2][2];
#pragma unroll
            for (int rr = 0; rr < 2; rr++) {
                const int mm = mA + 8 * rr;
                s[rr][0] = C0f * sh0r[rr] * x0s[mm * 33 + 2 * j];
                s[rr][1] = C0f * sh0r[rr] * x0s[mm * 33 + 2 * j + 1];
            }
#pragma unroll
            for (int t = 0; t < 8; t++) {
                const int gs = t >> 2;
                const int cb = 64 * j + 8 * t + q2;
                const float b20 = b2s[cb], b21 = b2s[cb + 1];
                const int sl = (t & 3) * 2;
                accO[0][sl]     += s[0][gs] * (c[t][0] + b20);
                accO[0][sl + 1] += s[0][gs] * (c[t][1] + b21);
                accO[1][sl]     += s[1][gs] * (c[t][2] + b20);
                accO[1][sl + 1] += s[1][gs] * (c[t][3] + b21);
            }
        } else if (j < 24) {                        // block2 -> out0
            float s[2][2];
#pragma unroll
            for (int rr = 0; rr < 2; rr++) {
                const int mm = mA + 8 * rr;
#pragma unroll
                for (int gs = 0; gs < 2; gs++) {
                    const int u = 2 * (j - 16) + gs;
                    s[rr][gs] = C0IS3 * (x1s[mm * 49 + 3 * u] * sh1r[rr][0]
                                       + x1s[mm * 49 + 3 * u + 1] * sh1r[rr][1]
                                       + x1s[mm * 49 + 3 * u + 2] * sh1r[rr][2]);
                }
            }
#pragma unroll
            for (int t = 0; t < 8; t++) {
                const int gs = t >> 2;
                const int cb = 64 * j + 8 * t + q2;
                const float b20 = b2s[cb], b21 = b2s[cb + 1];
                const int sl = (t & 3) * 2;
                accO[0][sl]     += s[0][gs] * (c[t][0] + b20);
                accO[0][sl + 1] += s[0][gs] * (c[t][1] + b21);
                accO[1][sl]     += s[1][gs] * (c[t][2] + b20);
                accO[1][sl + 1] += s[1][gs] * (c[t][3] + b21);
            }
        } else if (j < 32) {                        // block3 -> t3
            float s3[2][2][2];
#pragma unroll
            for (int rr = 0; rr < 2; rr++) {
                const int mm = mA + 8 * rr;
#pragma unroll
                for (int gs = 0; gs < 2; gs++)
#pragma unroll
                    for (int us = 0; us < 2; us++)
                        s3[rr][gs][us] = C1IS3 * x0s[mm * 33 + (j - 24) * 4 + 2 * gs + us];
            }
#pragma unroll
            for (int t = 0; t < 8; t++) {
                const int gs = t >> 2;
                const int us = (t >> 1) & 1;
                const int cb = 64 * j + 8 * t + q2;
                const float b20 = b2s[cb], b21 = b2s[cb + 1];
                const int sl = (t & 1) * 2;
                accT3[0][sl]     += s3[0][gs][us] * (c[t][0] + b20);
                accT3[0][sl + 1] += s3[0][gs][us] * (c[t][1] + b21);
                accT3[1][sl]     += s3[1][gs][us] * (c[t][2] + b20);
                accT3[1][sl + 1] += s3[1][gs][us] * (c[t][3] + b21);
            }
        } else {                                    // block4 / block5 -> out1
            float av[2][2][2][3];
            const bool is5 = (j >= 36);
#pragma unroll
            for (int rr = 0; rr < 2; rr++) {
                const int mm = mA + 8 * rr;
#pragma unroll
                for (int gs = 0; gs < 2; gs++)
#pragma unroll
                    for (int us = 0; us < 2; us++) {
                        if (!is5) {
                            const int u = (j - 32) * 4 + 2 * gs + us;
                            const float kb = C1IS3 * sh0r[rr];
                            av[rr][gs][us][0] = kb * x1s[mm * 49 + 3 * u + 0];
                            av[rr][gs][us][1] = kb * x1s[mm * 49 + 3 * u + 1];
                            av[rr][gs][us][2] = kb * x1s[mm * 49 + 3 * u + 2];
                        } else {
                            const int u = (j - 36) * 4 + 2 * gs + us;
                            const float xx = x1s[mm * 49 + 3 * u + 0];
                            const float xy = x1s[mm * 49 + 3 * u + 1];
                            const float xz = x1s[mm * 49 + 3 * u + 2];
                            av[rr][gs][us][0] = C1IS6 * (xy * sh1r[rr][2] - xz * sh1r[rr][1]);
                            av[rr][gs][us][1] = C1IS6 * (xz * sh1r[rr][0] - xx * sh1r[rr][2]);
                            av[rr][gs][us][2] = C1IS6 * (xx * sh1r[rr][1] - xy * sh1r[rr][0]);
                        }
                    }
            }
#pragma unroll
            for (int t = 0; t < 8; t++) {
                const int gs = t >> 2;
                const int us = (t >> 1) & 1;
                const int cb = 64 * j + 8 * t + q2;
                const float b20 = b2s[cb], b21 = b2s[cb + 1];
                const int sl = (t & 1) * 2;
                const float D00 = c[t][0] + b20, D01 = c[t][1] + b21;
                const float D10 = c[t][2] + b20, D11 = c[t][3] + b21;
#pragma unroll
                for (int k = 0; k < 3; k++) {
                    accV[0][sl][k]     += av[0][gs][us][k] * D00;
                    accV[0][sl + 1][k] += av[0][gs][us][k] * D01;
                    accV[1][sl][k]     += av[1][gs][us][k] * D10;
                    accV[1][sl + 1][k] += av[1][gs][us][k] * D11;
                }
            }
        }
    }

    // ---- scatter ----
#pragma unroll
    for (int rr = 0; rr < 2; rr++) {
        const int mm = mA + 8 * rr;
        const int src = srcs[mm];
        float* segp = g_seg + (size_t)src * NODE_DIM;
#pragma unroll
        for (int tt = 0; tt < 4; tt++)
#pragma unroll
            for (int b = 0; b < 2; b++)
                atomicAdd(segp + 8 * tt + q2 + b, accO[rr][tt * 2 + b]);
#pragma unroll
        for (int ws = 0; ws < 2; ws++)
#pragma unroll
            for (int b = 0; b < 2; b++) {
                const int wc = 8 * ws + q2 + b;
#pragma unroll
                for (int k = 0; k < 3; k++)
                    atomicAdd(segp + 32 + 3 * wc + k,
                              fmaf(sh1r[rr][k], accT3[rr][ws * 2 + b], accV[rr][ws * 2 + b][k]));
            }
    }
}

// ---------------- node epilogue ----------------
__global__ void node_kernel(const float* __restrict__ node_attr,
                            const float* __restrict__ mean_shift,
                            const float* __restrict__ aw,
                            const float* __restrict__ ab,
                            float* __restrict__ out) {
    const int warp = (blockIdx.x * blockDim.x + threadIdx.x) >> 5;
    const int lane = threadIdx.x & 31;
    if (warp >= N_NODES) return;
    const unsigned full = 0xFFFFFFFFu;

    const float inv = 1.0f / fmaxf(g_cnt[warp], 1.0f);
    const float* seg = g_seg + (size_t)warp * NODE_DIM;
    const float* na  = node_attr + (size_t)warp * NODE_DIM;

    float o0 = seg[lane] * inv + na[lane];
    float mval = o0;
#pragma unroll
    for (int off = 16; off; off >>= 1) mval += __shfl_xor_sync(full, mval, off);
    mval *= (1.0f / 32.0f);
    const float f0 = o0 - mval * mean_shift[lane];
    float s = f0 * f0;
#pragma unroll
    for (int off = 16; off; off >>= 1) s += __shfl_xor_sync(full, s, off);
    const float sc0 = rsqrtf(s * (1.0f / 32.0f) + EPS_LN) * aw[lane];
    out[(size_t)warp * NODE_DIM + lane] = f0 * sc0 + ab[lane];

    float vx = 0.0f, vy = 0.0f, vz = 0.0f, msv = 0.0f;
    if (lane < 16) {
        vx = seg[32 + 3 * lane + 0] * inv + na[32 + 3 * lane + 0];
        vy = seg[32 + 3 * lane + 1] * inv + na[32 + 3 * lane + 1];
        vz = seg[32 + 3 * lane + 2] * inv + na[32 + 3 * lane + 2];
        msv = mean_shift[32 + lane];
    }
    float mx = vx, my = vy, mz = vz;
#pragma unroll
    for (int off = 16; off; off >>= 1) {
        mx += __shfl_xor_sync(full, mx, off);
        my += __shfl_xor_sync(full, my, off);
        mz += __shfl_xor_sync(full, mz, off);
    }
    mx *= (1.0f / 16.0f); my *= (1.0f / 16.0f); mz *= (1.0f / 16.0f);
    const float fx = vx - mx * msv;
    const float fy = vy - my * msv;
    const float fz = vz - mz * msv;
    float sq = (lane < 16) ? (fx * fx + fy * fy + fz * fz) : 0.0f;
#pragma unroll
    for (int off = 16; off; off >>= 1) sq += __shfl_xor_sync(full, sq, off);
    if (lane < 16) {
        const float sc1 = rsqrtf(sq * (1.0f / 48.0f) + EPS_LN) * aw[32 + lane];
        out[(size_t)warp * NODE_DIM + 32 + 3 * lane + 0] = fx * sc1;
        out[(size_t)warp * NODE_DIM + 32 + 3 * lane + 1] = fy * sc1;
        out[(size_t)warp * NODE_DIM + 32 + 3 * lane + 2] = fz * sc1;
    }
}

// ---------------- launch ----------------
extern "C" void kernel_launch(void* const* d_in, const int* in_sizes, int n_in,
                              void* d_out, int out_size) {
    const float* node_attr  = (const float*)d_in[0];
    const float* edge_attr  = (const float*)d_in[1];
    const float* edge_sh    = (const float*)d_in[2];
    const float* fc_w1      = (const float*)d_in[3];
    const float* fc_b1      = (const float*)d_in[4];
    const float* fc_w2      = (const float*)d_in[5];
    const float* fc_b2      = (const float*)d_in[6];
    const float* mean_shift = (const float*)d_in[7];
    const float* aw         = (const float*)d_in[8];
    const float* ab         = (const float*)d_in[9];
    const int*   edge_index = (const int*)d_in[10];
    float* out = (float*)d_out;

    cudaFuncSetAttribute(gemm1_kernel, cudaFuncAttributeMaxDynamicSharedMemorySize, (int)GEMM1_SMEM);
    cudaFuncSetAttribute(edge_kernel,  cudaFuncAttributeMaxDynamicSharedMemorySize, (int)EDGE_SMEM);

    zero_kernel<<<160, 256>>>();
    bprep_kernel<<<320, 256>>>(fc_w2);
    gemm1_kernel<<<NTILES, 512, GEMM1_SMEM>>>(edge_attr, fc_w1, fc_b1);
    edge_kernel<<<NTILES, 256, EDGE_SMEM>>>(node_attr, edge_sh, fc_b2, edge_index);
    node_kernel<<<(N_NODES * 32 + 255) / 256, 256>>>(node_attr, mean_shift, aw, ab, out);
}

// round 4
// speedup vs baseline: 5.7914x; 1.5585x over previous
#include <cuda_runtime.h>
#include <cuda_bf16.h>
#include <cuda_fp16.h>
#include <cstdint>
#include <cstddef>

#define N_NODES 20000
#define N_EDGES 160000
#define MUL0 32
#define MUL1 16
#define NODE_DIM 80
#define EDGE_FEAT 128
#define HIDDEN 128
#define W_NUMEL 2560
#define MTILE 64                      // edges per CTA (edge kernel)
#define NTILES (N_EDGES / MTILE)      // 2500
#define NCHUNK 64                     // fc_w2 cols per chunk
#define NCHUNKS (W_NUMEL / NCHUNK)    // 40

#define C0f   0.14433756729740643f
#define C1f   0.21650635094610965f
#define IS3f  0.5773502691896258f
#define IS6f  0.40824829046386296f
#define C0IS3 (C0f * IS3f)
#define C1IS3 (C1f * IS3f)
#define C1IS6 (C1f * IS6f)
#define EPS_LN 1e-5f

// ---------------- device scratch ----------------
__device__ __align__(16) __half g_Ahi[(size_t)N_EDGES * HIDDEN];   // h hi fp16, [e][k]
__device__ __align__(16) __half g_Alo[(size_t)N_EDGES * HIDDEN];   // h lo fp16
__device__ __align__(16) __half g_Bf16[(size_t)W_NUMEL * HIDDEN];  // W2^T fp16 [n][k]
__device__ __align__(16) __nv_bfloat16 g_W1hi[HIDDEN * HIDDEN];    // W1^T bf16 [n][k]
__device__ __align__(16) __nv_bfloat16 g_W1lo[HIDDEN * HIDDEN];
__device__ float g_seg[(size_t)N_NODES * NODE_DIM];
__device__ float g_cnt[N_NODES];

// ---------------- PTX helpers ----------------
__device__ __forceinline__ uint32_t smem_u32(const void* p) {
    uint32_t a;
    asm("{ .reg .u64 t; cvta.to.shared.u64 t, %1; cvt.u32.u64 %0, t; }" : "=r"(a) : "l"(p));
    return a;
}
__device__ __forceinline__ void ldsm_x4(uint32_t* r, uint32_t addr) {
    asm volatile("ldmatrix.sync.aligned.m8n8.x4.shared.b16 {%0,%1,%2,%3}, [%4];"
        : "=r"(r[0]), "=r"(r[1]), "=r"(r[2]), "=r"(r[3]) : "r"(addr));
}
__device__ __forceinline__ void mma_bf16(float* c, const uint32_t* a, uint32_t b0, uint32_t b1) {
    asm volatile("mma.sync.aligned.m16n8k16.row.col.f32.bf16.bf16.f32 "
        "{%0,%1,%2,%3}, {%4,%5,%6,%7}, {%8,%9}, {%0,%1,%2,%3};"
        : "+f"(c[0]), "+f"(c[1]), "+f"(c[2]), "+f"(c[3])
        : "r"(a[0]), "r"(a[1]), "r"(a[2]), "r"(a[3]), "r"(b0), "r"(b1));
}
__device__ __forceinline__ void mma_f16(float* c, const uint32_t* a, uint32_t b0, uint32_t b1) {
    asm volatile("mma.sync.aligned.m16n8k16.row.col.f32.f16.f16.f32 "
        "{%0,%1,%2,%3}, {%4,%5,%6,%7}, {%8,%9}, {%0,%1,%2,%3};"
        : "+f"(c[0]), "+f"(c[1]), "+f"(c[2]), "+f"(c[3])
        : "r"(a[0]), "r"(a[1]), "r"(a[2]), "r"(a[3]), "r"(b0), "r"(b1));
}
__device__ __forceinline__ void cp_async16(uint32_t smem_addr, const void* gptr) {
    asm volatile("cp.async.ca.shared.global [%0], [%1], 16;" :: "r"(smem_addr), "l"(gptr));
}
#define CP_COMMIT() asm volatile("cp.async.commit_group;" ::: "memory")
#define CP_WAIT_0() asm volatile("cp.async.wait_group 0;" ::: "memory")

// ---------------- prep: zero scratch, split W1^T (bf16), W2^T (fp16) ----------------
__global__ void prep_kernel(const float* __restrict__ fc_w1,
                            const float* __restrict__ fc_w2) {
    const int tid = blockIdx.x * blockDim.x + threadIdx.x;
    const int stride = gridDim.x * blockDim.x;
    for (int i = tid; i < N_NODES * NODE_DIM; i += stride) g_seg[i] = 0.0f;
    for (int i = tid; i < N_NODES; i += stride) g_cnt[i] = 0.0f;
    for (int i = tid; i < HIDDEN * HIDDEN; i += stride) {
        const int n = i >> 7, k = i & 127;
        const float w = fc_w1[k * HIDDEN + n];
        const __nv_bfloat16 hi = __float2bfloat16(w);
        g_W1hi[i] = hi;
        g_W1lo[i] = __float2bfloat16(w - __bfloat162float(hi));
    }
    for (int i = tid; i < HIDDEN * W_NUMEL; i += stride) {
        const int n = i >> 7, k = i & 127;
        g_Bf16[i] = __float2half_rn(fc_w2[(size_t)k * W_NUMEL + n]);
    }
}

// ---------------- GEMM1 (tensor, bf16 3-pass): h = relu(edge_attr @ fc_w1 + b1) ----------------
// smem: Ahi bf16[128][272] @0, Alo @34816, Whi @69632, Wlo @104448, b1 @139264
#define G1_AHI 0
#define G1_ALO 34816
#define G1_WHI 69632
#define G1_WLO 104448
#define G1_B1  139264
#define G1_SMEM 139776
#define ROWB 272

__global__ __launch_bounds__(256, 1)
void gemm1_kernel(const float* __restrict__ edge_attr,
                  const float* __restrict__ fc_b1) {
    extern __shared__ char smc[];
    const uint32_t smb = smem_u32(smc);
    const int tid = threadIdx.x;
    const int w = tid >> 5;
    const int lane = tid & 31;
    const int e0 = blockIdx.x * 128;

    // W1 hi/lo via cp.async
#pragma unroll
    for (int it = 0; it < 8; it++) {
        const int i = tid + it * 256;           // 0..2047 = row(128) x kc(16)
        const int row = i >> 4, kc = i & 15;
        cp_async16(smb + G1_WHI + row * ROWB + kc * 16, g_W1hi + row * HIDDEN + kc * 8);
        cp_async16(smb + G1_WLO + row * ROWB + kc * 16, g_W1lo + row * HIDDEN + kc * 8);
    }
    CP_COMMIT();

    // stage A: fp32 -> bf16 hi/lo
    const float4* ga = (const float4*)(edge_attr + (size_t)e0 * EDGE_FEAT);
#pragma unroll
    for (int it = 0; it < 16; it++) {
        const int i = tid + it * 256;           // 0..4095 = row(128) x kc4(32)
        const int row = i >> 5, kc4 = i & 31;
        const float4 v = ga[i];
        __nv_bfloat162 h0 = __floats2bfloat162_rn(v.x, v.y);
        __nv_bfloat162 h1 = __floats2bfloat162_rn(v.z, v.w);
        __nv_bfloat162 l0 = __floats2bfloat162_rn(v.x - __bfloat162float(h0.x), v.y - __bfloat162float(h0.y));
        __nv_bfloat162 l1 = __floats2bfloat162_rn(v.z - __bfloat162float(h1.x), v.w - __bfloat162float(h1.y));
        char* dh = smc + G1_AHI + row * ROWB + kc4 * 8;
        char* dl = smc + G1_ALO + row * ROWB + kc4 * 8;
        *(__nv_bfloat162*)(dh) = h0; *(__nv_bfloat162*)(dh + 4) = h1;
        *(__nv_bfloat162*)(dl) = l0; *(__nv_bfloat162*)(dl + 4) = l1;
    }
    if (tid < 128) ((float*)(smc + G1_B1))[tid] = fc_b1[tid];
    CP_WAIT_0();
    __syncthreads();

    const int q2 = 2 * (lane & 3);
    const int r8 = lane >> 2;
    const int mA = 16 * w + r8;

    const uint32_t aRow = (uint32_t)(16 * w + (lane & 7) + ((lane >> 3) & 1) * 8);
    const uint32_t aK = (uint32_t)(((lane >> 4) & 1) * 16);
    const uint32_t aHiB = smb + G1_AHI + aRow * ROWB + aK;
    const uint32_t aLoB = smb + G1_ALO + aRow * ROWB + aK;
    const uint32_t bRow = (uint32_t)((lane & 7) + ((lane >> 4) & 1) * 8);
    const uint32_t bK = (uint32_t)(((lane >> 3) & 1) * 16);
    const uint32_t wHiB = smb + G1_WHI + bRow * ROWB + bK;
    const uint32_t wLoB = smb + G1_WLO + bRow * ROWB + bK;

    float c[16][4];
#pragma unroll
    for (int t = 0; t < 16; t++)
#pragma unroll
        for (int i = 0; i < 4; i++) c[t][i] = 0.0f;

#pragma unroll
    for (int ks = 0; ks < 8; ks++) {
        uint32_t ah[4], al[4];
        ldsm_x4(ah, aHiB + ks * 32);
        ldsm_x4(al, aLoB + ks * 32);
#pragma unroll
        for (int tp = 0; tp < 8; tp++) {
            uint32_t wh[4], wl[4];
            ldsm_x4(wh, wHiB + tp * (16 * ROWB) + ks * 32);
            ldsm_x4(wl, wLoB + tp * (16 * ROWB) + ks * 32);
            mma_bf16(c[2 * tp],     ah, wh[0], wh[1]);
            mma_bf16(c[2 * tp],     ah, wl[0], wl[1]);
            mma_bf16(c[2 * tp],     al, wh[0], wh[1]);
            mma_bf16(c[2 * tp + 1], ah, wh[2], wh[3]);
            mma_bf16(c[2 * tp + 1], ah, wl[2], wl[3]);
            mma_bf16(c[2 * tp + 1], al, wh[2], wh[3]);
        }
    }

    // bias + relu + fp16 hi/lo split -> global
    const float* b1s = (const float*)(smc + G1_B1);
#pragma unroll
    for (int t = 0; t < 16; t++) {
        const int col = 8 * t + q2;
        const float bb0 = b1s[col], bb1 = b1s[col + 1];
#pragma unroll
        for (int rr = 0; rr < 2; rr++) {
            const int mm = mA + 8 * rr;
            float v0 = fmaxf(c[t][2 * rr + 0] + bb0, 0.0f);
            float v1 = fmaxf(c[t][2 * rr + 1] + bb1, 0.0f);
            __half h0 = __float2half_rn(v0), h1 = __float2half_rn(v1);
            __half l0 = __float2half_rn(v0 - __half2float(h0));
            __half l1 = __float2half_rn(v1 - __half2float(h1));
            const size_t off = (size_t)(e0 + mm) * HIDDEN + col;
            *(__half2*)(g_Ahi + off) = __halves2half2(h0, h1);
            *(__half2*)(g_Alo + off) = __halves2half2(l0, l1);
        }
    }
}

// ---------------- fused fp16 HMMA GEMM2 + tensor product + scatter ----------------
// smem bytes: Ahi[64][272]@0, Alo@17408, B 2x[64][272]@34816,
//             b2s@69632(10240), x0s@79872(64*33f), x1s@88320(64*49f),
//             shs@100864(64*4f), srcs@101888(64 int)
#define OFF_AHI 0
#define OFF_ALO 17408
#define OFF_B   34816
#define BBUF    17408
#define OFF_B2  69632
#define OFF_X0  79872
#define OFF_X1  88320
#define OFF_SH  100864
#define OFF_SRC 101888
#define EDGE_SMEM 102144

__global__ __launch_bounds__(256, 2)
void edge_kernel(const float* __restrict__ node_attr,
                 const float* __restrict__ edge_sh,
                 const float* __restrict__ fc_b2,
                 const int*   __restrict__ edge_index) {
    extern __shared__ char smc[];
    const uint32_t smb = smem_u32(smc);
    float* b2s = (float*)(smc + OFF_B2);
    float* x0s = (float*)(smc + OFF_X0);
    float* x1s = (float*)(smc + OFF_X1);
    float* shs = (float*)(smc + OFF_SH);
    int*  srcs = (int*)(smc + OFF_SRC);

    const int tid  = threadIdx.x;
    const int w    = tid >> 5;
    const int lane = tid & 31;
    const int rb   = w & 3;          // row block: rows 16rb..16rb+15
    const int ch   = w >> 2;         // col half of the 64-col chunk
    const int e0 = blockIdx.x * MTILE;

    // issue B chunk 0
#pragma unroll
    for (int it = 0; it < 4; it++) {
        const int i = tid + it * 256;       // 0..1023 = row(64) x kc(16)
        const int row = i >> 4, kc = i & 15;
        cp_async16(smb + OFF_B + row * ROWB + kc * 16,
                   g_Bf16 + (size_t)row * HIDDEN + kc * 8);
    }
    CP_COMMIT();

    // stage A hi/lo
    {
        const int4* gh = (const int4*)(g_Ahi + (size_t)e0 * HIDDEN);
        const int4* gl = (const int4*)(g_Alo + (size_t)e0 * HIDDEN);
#pragma unroll
        for (int it = 0; it < 4; it++) {
            const int i = tid + it * 256;   // row(64) x kc(16)
            const int row = i >> 4, kc = i & 15;
            *(int4*)(smc + OFF_AHI + row * ROWB + kc * 16) = gh[i];
            *(int4*)(smc + OFF_ALO + row * ROWB + kc * 16) = gl[i];
        }
    }
    for (int i = tid; i < W_NUMEL; i += 256) b2s[i] = fc_b2[i];

    // gather per-edge vectors
    if (tid < MTILE) {
        const int eg  = e0 + tid;
        const int src = edge_index[eg];
        const int dst = edge_index[N_EDGES + eg];
        srcs[tid] = src;
        atomicAdd(&g_cnt[src], 1.0f);
        const float4* na = (const float4*)(node_attr + (size_t)dst * NODE_DIM);
#pragma unroll
        for (int q = 0; q < 8; q++) {
            const float4 v = na[q];
            x0s[tid * 33 + 4 * q + 0] = v.x;
            x0s[tid * 33 + 4 * q + 1] = v.y;
            x0s[tid * 33 + 4 * q + 2] = v.z;
            x0s[tid * 33 + 4 * q + 3] = v.w;
        }
#pragma unroll
        for (int q = 0; q < 12; q++) {
            const float4 v = na[8 + q];
            x1s[tid * 49 + 4 * q + 0] = v.x;
            x1s[tid * 49 + 4 * q + 1] = v.y;
            x1s[tid * 49 + 4 * q + 2] = v.z;
            x1s[tid * 49 + 4 * q + 3] = v.w;
        }
        const float4 sh4 = *(const float4*)(edge_sh + (size_t)eg * 4);
        shs[tid * 4 + 0] = sh4.x;
        shs[tid * 4 + 1] = sh4.y;
        shs[tid * 4 + 2] = sh4.z;
        shs[tid * 4 + 3] = sh4.w;
    }

    const int q2 = 2 * (lane & 3);
    const int r8 = lane >> 2;
    const int mA = 16 * rb + r8;            // rows mA, mA+8

    const uint32_t aRow = (uint32_t)(16 * rb + (lane & 7) + ((lane >> 3) & 1) * 8);
    const uint32_t aK = (uint32_t)(((lane >> 4) & 1) * 16);
    const uint32_t aHiB = smb + OFF_AHI + aRow * ROWB + aK;
    const uint32_t aLoB = smb + OFF_ALO + aRow * ROWB + aK;
    const uint32_t bRow = (uint32_t)(32 * ch + (lane & 7) + ((lane >> 4) & 1) * 8);
    const uint32_t bK = (uint32_t)(((lane >> 3) & 1) * 16);
    const uint32_t bBase0 = smb + OFF_B + bRow * ROWB + bK;

    float sh0r[2], sh1r[2][3];
#pragma unroll
    for (int rr = 0; rr < 2; rr++) { sh0r[rr] = 0.f; sh1r[rr][0] = sh1r[rr][1] = sh1r[rr][2] = 0.f; }

    float accO[2][8], accT3[2][4], accV[2][4][3];
#pragma unroll
    for (int rr = 0; rr < 2; rr++) {
#pragma unroll
        for (int i = 0; i < 8; i++) accO[rr][i] = 0.0f;
#pragma unroll
        for (int i = 0; i < 4; i++) {
            accT3[rr][i] = 0.0f;
#pragma unroll
            for (int k = 0; k < 3; k++) accV[rr][i][k] = 0.0f;
        }
    }

    bool shLoaded = false;

    for (int j = 0; j < NCHUNKS; j++) {
        CP_WAIT_0();
        __syncthreads();
        if (!shLoaded) {        // after first barrier shs is valid
#pragma unroll
            for (int rr = 0; rr < 2; rr++) {
                const int mm = mA + 8 * rr;
                sh0r[rr] = shs[mm * 4 + 0];
                sh1r[rr][0] = shs[mm * 4 + 1];
                sh1r[rr][1] = shs[mm * 4 + 2];
                sh1r[rr][2] = shs[mm * 4 + 3];
            }
            shLoaded = true;
        }
        // prefetch chunk j+1 (into buffer read two iters ago — safe post-barrier)
        if (j + 1 < NCHUNKS) {
            const uint32_t sb = smb + OFF_B + ((j + 1) & 1) * BBUF;
            const __half* gp0 = g_Bf16 + (size_t)(j + 1) * NCHUNK * HIDDEN;
#pragma unroll
            for (int it = 0; it < 4; it++) {
                const int i = tid + it * 256;
                const int row = i >> 4, kc = i & 15;
                cp_async16(sb + row * ROWB + kc * 16, gp0 + (size_t)row * HIDDEN + kc * 8);
            }
            CP_COMMIT();
        }

        // ---- MMA: warp computes rows [16rb,16rb+16) x cols [32ch, 32ch+32) ----
        const uint32_t bb = bBase0 + (j & 1) * BBUF;
        float c[4][4];
#pragma unroll
        for (int t = 0; t < 4; t++)
#pragma unroll
            for (int i = 0; i < 4; i++) c[t][i] = 0.0f;

#pragma unroll
        for (int ks = 0; ks < 8; ks++) {
            uint32_t ah[4], al[4];
            ldsm_x4(ah, aHiB + ks * 32);
            ldsm_x4(al, aLoB + ks * 32);
#pragma unroll
            for (int tp = 0; tp < 2; tp++) {
                uint32_t bf[4];
                ldsm_x4(bf, bb + tp * (16 * ROWB) + ks * 32);
                mma_f16(c[2 * tp],     ah, bf[0], bf[1]);
                mma_f16(c[2 * tp],     al, bf[0], bf[1]);
                mma_f16(c[2 * tp + 1], ah, bf[2], bf[3]);
                mma_f16(c[2 * tp + 1], al, bf[2], bf[3]);
            }
        }

        // ---- epilogue: this warp's 32 cols = group g ----
        const int g = 2 * j + ch;
        const float* b2g = b2s + 32 * g;

        if (g < 32) {                               // block1 -> out0 (u = g)
            float s[2];
#pragma unroll
            for (int rr = 0; rr < 2; rr++)
                s[rr] = C0f * sh0r[rr] * x0s[(mA + 8 * rr) * 33 + g];
#pragma unroll
            for (int t = 0; t < 4; t++) {
                const float b20 = b2g[8 * t + q2], b21 = b2g[8 * t + q2 + 1];
                accO[0][2 * t]     += s[0] * (c[t][0] + b20);
                accO[0][2 * t + 1] += s[0] * (c[t][1] + b21);
                accO[1][2 * t]     += s[1] * (c[t][2] + b20);
                accO[1][2 * t + 1] += s[1] * (c[t][3] + b21);
            }
        } else if (g < 48) {                        // block2 -> out0 (u = g-32)
            const int u = g - 32;
            float s[2];
#pragma unroll
            for (int rr = 0; rr < 2; rr++) {
                const int mm = mA + 8 * rr;
                s[rr] = C0IS3 * (x1s[mm * 49 + 3 * u] * sh1r[rr][0]
                               + x1s[mm * 49 + 3 * u + 1] * sh1r[rr][1]
                               + x1s[mm * 49 + 3 * u + 2] * sh1r[rr][2]);
            }
#pragma unroll
            for (int t = 0; t < 4; t++) {
                const float b20 = b2g[8 * t + q2], b21 = b2g[8 * t + q2 + 1];
                accO[0][2 * t]     += s[0] * (c[t][0] + b20);
                accO[0][2 * t + 1] += s[0] * (c[t][1] + b21);
                accO[1][2 * t]     += s[1] * (c[t][2] + b20);
                accO[1][2 * t + 1] += s[1] * (c[t][3] + b21);
            }
        } else if (g < 64) {                        // block3 -> t3 (u = 2(g-48)+us)
            const int u0 = 2 * (g - 48);
            float s[2][2];
#pragma unroll
            for (int rr = 0; rr < 2; rr++) {
                const int mm = mA + 8 * rr;
                s[rr][0] = C1IS3 * x0s[mm * 33 + u0];
                s[rr][1] = C1IS3 * x0s[mm * 33 + u0 + 1];
            }
#pragma unroll
            for (int t = 0; t < 4; t++) {
                const int us = t >> 1;
                const int sl = 2 * (t & 1);
                const float b20 = b2g[8 * t + q2], b21 = b2g[8 * t + q2 + 1];
                accT3[0][sl]     += s[0][us] * (c[t][0] + b20);
                accT3[0][sl + 1] += s[0][us] * (c[t][1] + b21);
                accT3[1][sl]     += s[1][us] * (c[t][2] + b20);
                accT3[1][sl + 1] += s[1][us] * (c[t][3] + b21);
            }
        } else {                                    // block4/5 -> out1
            const bool is5 = (g >= 72);
            const int u0 = is5 ? 2 * (g - 72) : 2 * (g - 64);
            float av[2][2][3];
#pragma unroll
            for (int rr = 0; rr < 2; rr++) {
                const int mm = mA + 8 * rr;
#pragma unroll
                for (int us = 0; us < 2; us++) {
                    const int u = u0 + us;
                    const float xx = x1s[mm * 49 + 3 * u + 0];
                    const float xy = x1s[mm * 49 + 3 * u + 1];
                    const float xz = x1s[mm * 49 + 3 * u + 2];
                    if (!is5) {
                        const float kb = C1IS3 * sh0r[rr];
                        av[rr][us][0] = kb * xx;
                        av[rr][us][1] = kb * xy;
                        av[rr][us][2] = kb * xz;
                    } else {
                        av[rr][us][0] = C1IS6 * (xy * sh1r[rr][2] - xz * sh1r[rr][1]);
                        av[rr][us][1] = C1IS6 * (xz * sh1r[rr][0] - xx * sh1r[rr][2]);
                        av[rr][us][2] = C1IS6 * (xx * sh1r[rr][1] - xy * sh1r[rr][0]);
                    }
                }
            }
#pragma unroll
            for (int t = 0; t < 4; t++) {
                const int us = t >> 1;
                const int sl = 2 * (t & 1);
                const float b20 = b2g[8 * t + q2], b21 = b2g[8 * t + q2 + 1];
                const float D00 = c[t][0] + b20, D01 = c[t][1] + b21;
                const float D10 = c[t][2] + b20, D11 = c[t][3] + b21;
#pragma unroll
                for (int k = 0; k < 3; k++) {
                    accV[0][sl][k]     += av[0][us][k] * D00;
                    accV[0][sl + 1][k] += av[0][us][k] * D01;
                    accV[1][sl][k]     += av[1][us][k] * D10;
                    accV[1][sl + 1][k] += av[1][us][k] * D11;
                }
            }
        }
    }

    // ---- scatter ----
#pragma unroll
    for (int rr = 0; rr < 2; rr++) {
        const int mm = mA + 8 * rr;
        const int src = srcs[mm];
        float* segp = g_seg + (size_t)src * NODE_DIM;
#pragma unroll
        for (int t = 0; t < 4; t++)
#pragma unroll
            for (int b = 0; b < 2; b++)
                atomicAdd(segp + 8 * t + q2 + b, accO[rr][2 * t + b]);
#pragma unroll
        for (int ws = 0; ws < 2; ws++)
#pragma unroll
            for (int b = 0; b < 2; b++) {
                const int wc = 8 * ws + q2 + b;
#pragma unroll
                for (int k = 0; k < 3; k++)
                    atomicAdd(segp + 32 + 3 * wc + k,
                              fmaf(sh1r[rr][k], accT3[rr][2 * ws + b], accV[rr][2 * ws + b][k]));
            }
    }
}

// ---------------- node epilogue ----------------
__global__ void node_kernel(const float* __restrict__ node_attr,
                            const float* __restrict__ mean_shift,
                            const float* __restrict__ aw,
                            const float* __restrict__ ab,
                            float* __restrict__ out) {
    const int warp = (blockIdx.x * blockDim.x + threadIdx.x) >> 5;
    const int lane = threadIdx.x & 31;
    if (warp >= N_NODES) return;
    const unsigned full = 0xFFFFFFFFu;

    const float inv = 1.0f / fmaxf(g_cnt[warp], 1.0f);
    const float* seg = g_seg + (size_t)warp * NODE_DIM;
    const float* na  = node_attr + (size_t)warp * NODE_DIM;

    float o0 = seg[lane] * inv + na[lane];
    float mval = o0;
#pragma unroll
    for (int off = 16; off; off >>= 1) mval += __shfl_xor_sync(full, mval, off);
    mval *= (1.0f / 32.0f);
    const float f0 = o0 - mval * mean_shift[lane];
    float s = f0 * f0;
#pragma unroll
    for (int off = 16; off; off >>= 1) s += __shfl_xor_sync(full, s, off);
    const float sc0 = rsqrtf(s * (1.0f / 32.0f) + EPS_LN) * aw[lane];
    out[(size_t)warp * NODE_DIM + lane] = f0 * sc0 + ab[lane];

    float vx = 0.0f, vy = 0.0f, vz = 0.0f, msv = 0.0f;
    if (lane < 16) {
        vx = seg[32 + 3 * lane + 0] * inv + na[32 + 3 * lane + 0];
        vy = seg[32 + 3 * lane + 1] * inv + na[32 + 3 * lane + 1];
        vz = seg[32 + 3 * lane + 2] * inv + na[32 + 3 * lane + 2];
        msv = mean_shift[32 + lane];
    }
    float mx = vx, my = vy, mz = vz;
#pragma unroll
    for (int off = 16; off; off >>= 1) {
        mx += __shfl_xor_sync(full, mx, off);
        my += __shfl_xor_sync(full, my, off);
        mz += __shfl_xor_sync(full, mz, off);
    }
    mx *= (1.0f / 16.0f); my *= (1.0f / 16.0f); mz *= (1.0f / 16.0f);
    const float fx = vx - mx * msv;
    const float fy = vy - my * msv;
    const float fz = vz - mz * msv;
    float sq = (lane < 16) ? (fx * fx + fy * fy + fz * fz) : 0.0f;
#pragma unroll
    for (int off = 16; off; off >>= 1) sq += __shfl_xor_sync(full, sq, off);
    if (lane < 16) {
        const float sc1 = rsqrtf(sq * (1.0f / 48.0f) + EPS_LN) * aw[32 + lane];
        out[(size_t)warp * NODE_DIM + 32 + 3 * lane + 0] = fx * sc1;
        out[(size_t)warp * NODE_DIM + 32 + 3 * lane + 1] = fy * sc1;
        out[(size_t)warp * NODE_DIM + 32 + 3 * lane + 2] = fz * sc1;
    }
}

// ---------------- launch ----------------
extern "C" void kernel_launch(void* const* d_in, const int* in_sizes, int n_in,
                              void* d_out, int out_size) {
    const float* node_attr  = (const float*)d_in[0];
    const float* edge_attr  = (const float*)d_in[1];
    const float* edge_sh    = (const float*)d_in[2];
    const float* fc_w1      = (const float*)d_in[3];
    const float* fc_b1      = (const float*)d_in[4];
    const float* fc_w2      = (const float*)d_in[5];
    const float* fc_b2      = (const float*)d_in[6];
    const float* mean_shift = (const float*)d_in[7];
    const float* aw         = (const float*)d_in[8];
    const float* ab         = (const float*)d_in[9];
    const int*   edge_index = (const int*)d_in[10];
    float* out = (float*)d_out;

    cudaFuncSetAttribute(gemm1_kernel, cudaFuncAttributeMaxDynamicSharedMemorySize, (int)G1_SMEM);
    cudaFuncSetAttribute(edge_kernel,  cudaFuncAttributeMaxDynamicSharedMemorySize, (int)EDGE_SMEM);

    prep_kernel<<<320, 256>>>(fc_w1, fc_w2);
    gemm1_kernel<<<N_EDGES / 128, 256, G1_SMEM>>>(edge_attr, fc_b1);
    edge_kernel<<<NTILES, 256, EDGE_SMEM>>>(node_attr, edge_sh, fc_b2, edge_index);
    node_kernel<<<(N_NODES * 32 + 255) / 256, 256>>>(node_attr, mean_shift, aw, ab, out);
}

// round 5
// speedup vs baseline: 7.2126x; 1.2454x over previous
#include <cuda_runtime.h>
#include <cuda_fp16.h>
#include <cstdint>
#include <cstddef>

#define N_NODES 20000
#define N_EDGES 160000
#define MUL0 32
#define MUL1 16
#define NODE_DIM 80
#define EDGE_FEAT 128
#define HIDDEN 128
#define W_NUMEL 2560
#define MTILE 64                      // edges per CTA (edge kernel)
#define NTILES (N_EDGES / MTILE)      // 2500
#define NCHUNK 64                     // fc_w2 cols per chunk
#define NCHUNKS (W_NUMEL / NCHUNK)    // 40

#define C0f   0.14433756729740643f
#define C1f   0.21650635094610965f
#define IS3f  0.5773502691896258f
#define IS6f  0.40824829046386296f
#define C0IS3 (C0f * IS3f)
#define C1IS3 (C1f * IS3f)
#define C1IS6 (C1f * IS6f)
#define EPS_LN 1e-5f

// ---------------- device scratch ----------------
__device__ __align__(16) __half g_A[(size_t)N_EDGES * HIDDEN];     // h fp16, [e][k]
__device__ __align__(16) __half g_Bf16[(size_t)W_NUMEL * HIDDEN];  // W2^T fp16 [n][k]
__device__ __align__(16) __half g_W1f16[HIDDEN * HIDDEN];          // W1^T fp16 [n][k]
__device__ float g_seg[(size_t)N_NODES * NODE_DIM];
__device__ float g_cnt[N_NODES];

// ---------------- PTX helpers ----------------
__device__ __forceinline__ uint32_t smem_u32(const void* p) {
    uint32_t a;
    asm("{ .reg .u64 t; cvta.to.shared.u64 t, %1; cvt.u32.u64 %0, t; }" : "=r"(a) : "l"(p));
    return a;
}
__device__ __forceinline__ void ldsm_x4(uint32_t* r, uint32_t addr) {
    asm volatile("ldmatrix.sync.aligned.m8n8.x4.shared.b16 {%0,%1,%2,%3}, [%4];"
        : "=r"(r[0]), "=r"(r[1]), "=r"(r[2]), "=r"(r[3]) : "r"(addr));
}
__device__ __forceinline__ void mma_f16(float* c, const uint32_t* a, uint32_t b0, uint32_t b1) {
    asm volatile("mma.sync.aligned.m16n8k16.row.col.f32.f16.f16.f32 "
        "{%0,%1,%2,%3}, {%4,%5,%6,%7}, {%8,%9}, {%0,%1,%2,%3};"
        : "+f"(c[0]), "+f"(c[1]), "+f"(c[2]), "+f"(c[3])
        : "r"(a[0]), "r"(a[1]), "r"(a[2]), "r"(a[3]), "r"(b0), "r"(b1));
}
__device__ __forceinline__ void cp_async16(uint32_t smem_addr, const void* gptr) {
    asm volatile("cp.async.ca.shared.global [%0], [%1], 16;" :: "r"(smem_addr), "l"(gptr));
}
#define CP_COMMIT() asm volatile("cp.async.commit_group;" ::: "memory")
#define CP_WAIT_0() asm volatile("cp.async.wait_group 0;" ::: "memory")

// ---------------- prep: zero scratch, W1^T fp16, W2^T fp16 ----------------
__global__ void prep_kernel(const float* __restrict__ fc_w1,
                            const float* __restrict__ fc_w2) {
    const int tid = blockIdx.x * blockDim.x + threadIdx.x;
    const int stride = gridDim.x * blockDim.x;
    for (int i = tid; i < N_NODES * NODE_DIM; i += stride) g_seg[i] = 0.0f;
    for (int i = tid; i < N_NODES; i += stride) g_cnt[i] = 0.0f;
    for (int i = tid; i < HIDDEN * HIDDEN; i += stride) {
        const int n = i >> 7, k = i & 127;
        g_W1f16[i] = __float2half_rn(fc_w1[k * HIDDEN + n]);
    }
    for (int i = tid; i < HIDDEN * W_NUMEL; i += stride) {
        const int n = i >> 7, k = i & 127;
        g_Bf16[i] = __float2half_rn(fc_w2[(size_t)k * W_NUMEL + n]);
    }
}

// ---------------- GEMM1 (fp16 2-pass: A hi/lo split, W single): h = relu(x@W1+b1) ----------------
// smem: Ahi fp16[128][272]@0, Alo@34816, W@69632, b1@104448(512) => 104960
#define G1_AHI 0
#define G1_ALO 34816
#define G1_W   69632
#define G1_B1  104448
#define G1_SMEM 104960
#define ROWB 272

__global__ __launch_bounds__(256, 2)
void gemm1_kernel(const float* __restrict__ edge_attr,
                  const float* __restrict__ fc_b1) {
    extern __shared__ char smc[];
    const uint32_t smb = smem_u32(smc);
    const int tid = threadIdx.x;
    const int w = tid >> 5;
    const int lane = tid & 31;
    const int e0 = blockIdx.x * 128;

    // W1 via cp.async
#pragma unroll
    for (int it = 0; it < 8; it++) {
        const int i = tid + it * 256;           // 0..2047 = row(128) x kc(16)
        const int row = i >> 4, kc = i & 15;
        cp_async16(smb + G1_W + row * ROWB + kc * 16, g_W1f16 + row * HIDDEN + kc * 8);
    }
    CP_COMMIT();

    // stage A: fp32 -> fp16 hi/lo
    const float4* ga = (const float4*)(edge_attr + (size_t)e0 * EDGE_FEAT);
#pragma unroll
    for (int it = 0; it < 16; it++) {
        const int i = tid + it * 256;           // 0..4095 = row(128) x kc4(32)
        const int row = i >> 5, kc4 = i & 31;
        const float4 v = ga[i];
        const __half hx = __float2half_rn(v.x), hy = __float2half_rn(v.y);
        const __half hz = __float2half_rn(v.z), hw = __float2half_rn(v.w);
        const __half lx = __float2half_rn(v.x - __half2float(hx));
        const __half ly = __float2half_rn(v.y - __half2float(hy));
        const __half lz = __float2half_rn(v.z - __half2float(hz));
        const __half lw = __float2half_rn(v.w - __half2float(hw));
        char* dh = smc + G1_AHI + row * ROWB + kc4 * 8;
        char* dl = smc + G1_ALO + row * ROWB + kc4 * 8;
        *(__half2*)(dh)     = __halves2half2(hx, hy);
        *(__half2*)(dh + 4) = __halves2half2(hz, hw);
        *(__half2*)(dl)     = __halves2half2(lx, ly);
        *(__half2*)(dl + 4) = __halves2half2(lz, lw);
    }
    if (tid < 128) ((float*)(smc + G1_B1))[tid] = fc_b1[tid];
    CP_WAIT_0();
    __syncthreads();

    const int q2 = 2 * (lane & 3);
    const int r8 = lane >> 2;
    const int mA = 16 * w + r8;

    const uint32_t aRow = (uint32_t)(16 * w + (lane & 7) + ((lane >> 3) & 1) * 8);
    const uint32_t aK = (uint32_t)(((lane >> 4) & 1) * 16);
    const uint32_t aHiB = smb + G1_AHI + aRow * ROWB + aK;
    const uint32_t aLoB = smb + G1_ALO + aRow * ROWB + aK;
    const uint32_t bRow = (uint32_t)((lane & 7) + ((lane >> 4) & 1) * 8);
    const uint32_t bK = (uint32_t)(((lane >> 3) & 1) * 16);
    const uint32_t wB = smb + G1_W + bRow * ROWB + bK;

    float c[16][4];
#pragma unroll
    for (int t = 0; t < 16; t++)
#pragma unroll
        for (int i = 0; i < 4; i++) c[t][i] = 0.0f;

#pragma unroll
    for (int ks = 0; ks < 8; ks++) {
        uint32_t ah[4], al[4];
        ldsm_x4(ah, aHiB + ks * 32);
        ldsm_x4(al, aLoB + ks * 32);
#pragma unroll
        for (int tp = 0; tp < 8; tp++) {
            uint32_t wf[4];
            ldsm_x4(wf, wB + tp * (16 * ROWB) + ks * 32);
            mma_f16(c[2 * tp],     ah, wf[0], wf[1]);
            mma_f16(c[2 * tp],     al, wf[0], wf[1]);
            mma_f16(c[2 * tp + 1], ah, wf[2], wf[3]);
            mma_f16(c[2 * tp + 1], al, wf[2], wf[3]);
        }
    }

    // bias + relu -> fp16 -> global
    const float* b1s = (const float*)(smc + G1_B1);
#pragma unroll
    for (int t = 0; t < 16; t++) {
        const int col = 8 * t + q2;
        const float bb0 = b1s[col], bb1 = b1s[col + 1];
#pragma unroll
        for (int rr = 0; rr < 2; rr++) {
            const int mm = mA + 8 * rr;
            const float v0 = fmaxf(c[t][2 * rr + 0] + bb0, 0.0f);
            const float v1 = fmaxf(c[t][2 * rr + 1] + bb1, 0.0f);
            *(__half2*)(g_A + (size_t)(e0 + mm) * HIDDEN + col) =
                __halves2half2(__float2half_rn(v0), __float2half_rn(v1));
        }
    }
}

// ---------------- fused fp16 HMMA GEMM2 (1-pass) + tensor product + scatter ----------------
// smem: A[64][272]@0 (17408), B 2x[64][272]@17408 (34816), b2s@52224 (10240),
//       x0s@62464 (8448), x1s@70912 (12544), shs@83456 (1024), srcs@84480 (256) => 84736
#define OFF_A   0
#define OFF_B   17408
#define BBUF    17408
#define OFF_B2  52224
#define OFF_X0  62464
#define OFF_X1  70912
#define OFF_SH  83456
#define OFF_SRC 84480
#define EDGE_SMEM 84736

__global__ __launch_bounds__(256, 2)
void edge_kernel(const float* __restrict__ node_attr,
                 const float* __restrict__ edge_sh,
                 const float* __restrict__ fc_b2,
                 const int*   __restrict__ edge_index) {
    extern __shared__ char smc[];
    const uint32_t smb = smem_u32(smc);
    float* b2s = (float*)(smc + OFF_B2);
    float* x0s = (float*)(smc + OFF_X0);
    float* x1s = (float*)(smc + OFF_X1);
    float* shs = (float*)(smc + OFF_SH);
    int*  srcs = (int*)(smc + OFF_SRC);

    const int tid  = threadIdx.x;
    const int w    = tid >> 5;
    const int lane = tid & 31;
    const int rb   = w & 3;          // row block: rows 16rb..16rb+15
    const int ch   = w >> 2;         // col half of the 64-col chunk
    const int e0 = blockIdx.x * MTILE;

    // issue B chunk 0 + A tile via cp.async
#pragma unroll
    for (int it = 0; it < 4; it++) {
        const int i = tid + it * 256;       // 0..1023 = row(64) x kc(16)
        const int row = i >> 4, kc = i & 15;
        cp_async16(smb + OFF_B + row * ROWB + kc * 16,
                   g_Bf16 + (size_t)row * HIDDEN + kc * 8);
        cp_async16(smb + OFF_A + row * ROWB + kc * 16,
                   g_A + (size_t)(e0 + row) * HIDDEN + kc * 8);
    }
    CP_COMMIT();

    for (int i = tid; i < W_NUMEL; i += 256) b2s[i] = fc_b2[i];

    // gather per-edge vectors
    if (tid < MTILE) {
        const int eg  = e0 + tid;
        const int src = edge_index[eg];
        const int dst = edge_index[N_EDGES + eg];
        srcs[tid] = src;
        atomicAdd(&g_cnt[src], 1.0f);
        const float4* na = (const float4*)(node_attr + (size_t)dst * NODE_DIM);
#pragma unroll
        for (int q = 0; q < 8; q++) {
            const float4 v = na[q];
            x0s[tid * 33 + 4 * q + 0] = v.x;
            x0s[tid * 33 + 4 * q + 1] = v.y;
            x0s[tid * 33 + 4 * q + 2] = v.z;
            x0s[tid * 33 + 4 * q + 3] = v.w;
        }
#pragma unroll
        for (int q = 0; q < 12; q++) {
            const float4 v = na[8 + q];
            x1s[tid * 49 + 4 * q + 0] = v.x;
            x1s[tid * 49 + 4 * q + 1] = v.y;
            x1s[tid * 49 + 4 * q + 2] = v.z;
            x1s[tid * 49 + 4 * q + 3] = v.w;
        }
        const float4 sh4 = *(const float4*)(edge_sh + (size_t)eg * 4);
        shs[tid * 4 + 0] = sh4.x;
        shs[tid * 4 + 1] = sh4.y;
        shs[tid * 4 + 2] = sh4.z;
        shs[tid * 4 + 3] = sh4.w;
    }

    const int q2 = 2 * (lane & 3);
    const int r8 = lane >> 2;
    const int mA = 16 * rb + r8;            // rows mA, mA+8

    const uint32_t aRow = (uint32_t)(16 * rb + (lane & 7) + ((lane >> 3) & 1) * 8);
    const uint32_t aK = (uint32_t)(((lane >> 4) & 1) * 16);
    const uint32_t aB = smb + OFF_A + aRow * ROWB + aK;
    const uint32_t bRow = (uint32_t)(32 * ch + (lane & 7) + ((lane >> 4) & 1) * 8);
    const uint32_t bK = (uint32_t)(((lane >> 3) & 1) * 16);
    const uint32_t bBase0 = smb + OFF_B + bRow * ROWB + bK;

    float sh0r[2], sh1r[2][3];
#pragma unroll
    for (int rr = 0; rr < 2; rr++) { sh0r[rr] = 0.f; sh1r[rr][0] = sh1r[rr][1] = sh1r[rr][2] = 0.f; }

    float accO[2][8], accT3[2][4], accV[2][4][3];
#pragma unroll
    for (int rr = 0; rr < 2; rr++) {
#pragma unroll
        for (int i = 0; i < 8; i++) accO[rr][i] = 0.0f;
#pragma unroll
        for (int i = 0; i < 4; i++) {
            accT3[rr][i] = 0.0f;
#pragma unroll
            for (int k = 0; k < 3; k++) accV[rr][i][k] = 0.0f;
        }
    }

    bool shLoaded = false;

    for (int j = 0; j < NCHUNKS; j++) {
        CP_WAIT_0();
        __syncthreads();
        if (!shLoaded) {
#pragma unroll
            for (int rr = 0; rr < 2; rr++) {
                const int mm = mA + 8 * rr;
                sh0r[rr] = shs[mm * 4 + 0];
                sh1r[rr][0] = shs[mm * 4 + 1];
                sh1r[rr][1] = shs[mm * 4 + 2];
                sh1r[rr][2] = shs[mm * 4 + 3];
            }
            shLoaded = true;
        }
        // prefetch chunk j+1
        if (j + 1 < NCHUNKS) {
            const uint32_t sb = smb + OFF_B + ((j + 1) & 1) * BBUF;
            const __half* gp0 = g_Bf16 + (size_t)(j + 1) * NCHUNK * HIDDEN;
#pragma unroll
            for (int it = 0; it < 4; it++) {
                const int i = tid + it * 256;
                const int row = i >> 4, kc = i & 15;
                cp_async16(sb + row * ROWB + kc * 16, gp0 + (size_t)row * HIDDEN + kc * 8);
            }
            CP_COMMIT();
        }

        // ---- MMA: rows [16rb,16rb+16) x cols [32ch, 32ch+32), single fp16 pass ----
        const uint32_t bb = bBase0 + (j & 1) * BBUF;
        float c[4][4];
#pragma unroll
        for (int t = 0; t < 4; t++)
#pragma unroll
            for (int i = 0; i < 4; i++) c[t][i] = 0.0f;

#pragma unroll
        for (int ks = 0; ks < 8; ks++) {
            uint32_t ah[4];
            ldsm_x4(ah, aB + ks * 32);
#pragma unroll
            for (int tp = 0; tp < 2; tp++) {
                uint32_t bf[4];
                ldsm_x4(bf, bb + tp * (16 * ROWB) + ks * 32);
                mma_f16(c[2 * tp],     ah, bf[0], bf[1]);
                mma_f16(c[2 * tp + 1], ah, bf[2], bf[3]);
            }
        }

        // ---- epilogue: this warp's 32 cols = group g ----
        const int g = 2 * j + ch;
        const float* b2g = b2s + 32 * g;

        if (g < 32) {                               // block1 -> out0 (u = g)
            float s[2];
#pragma unroll
            for (int rr = 0; rr < 2; rr++)
                s[rr] = C0f * sh0r[rr] * x0s[(mA + 8 * rr) * 33 + g];
#pragma unroll
            for (int t = 0; t < 4; t++) {
                const float b20 = b2g[8 * t + q2], b21 = b2g[8 * t + q2 + 1];
                accO[0][2 * t]     += s[0] * (c[t][0] + b20);
                accO[0][2 * t + 1] += s[0] * (c[t][1] + b21);
                accO[1][2 * t]     += s[1] * (c[t][2] + b20);
                accO[1][2 * t + 1] += s[1] * (c[t][3] + b21);
            }
        } else if (g < 48) {                        // block2 -> out0 (u = g-32)
            const int u = g - 32;
            float s[2];
#pragma unroll
            for (int rr = 0; rr < 2; rr++) {
                const int mm = mA + 8 * rr;
                s[rr] = C0IS3 * (x1s[mm * 49 + 3 * u] * sh1r[rr][0]
                               + x1s[mm * 49 + 3 * u + 1] * sh1r[rr][1]
                               + x1s[mm * 49 + 3 * u + 2] * sh1r[rr][2]);
            }
#pragma unroll
            for (int t = 0; t < 4; t++) {
                const float b20 = b2g[8 * t + q2], b21 = b2g[8 * t + q2 + 1];
                accO[0][2 * t]     += s[0] * (c[t][0] + b20);
                accO[0][2 * t + 1] += s[0] * (c[t][1] + b21);
                accO[1][2 * t]     += s[1] * (c[t][2] + b20);
                accO[1][2 * t + 1] += s[1] * (c[t][3] + b21);
            }
        } else if (g < 64) {                        // block3 -> t3
            const int u0 = 2 * (g - 48);
            float s[2][2];
#pragma unroll
            for (int rr = 0; rr < 2; rr++) {
                const int mm = mA + 8 * rr;
                s[rr][0] = C1IS3 * x0s[mm * 33 + u0];
                s[rr][1] = C1IS3 * x0s[mm * 33 + u0 + 1];
            }
#pragma unroll
            for (int t = 0; t < 4; t++) {
                const int us = t >> 1;
                const int sl = 2 * (t & 1);
                const float b20 = b2g[8 * t + q2], b21 = b2g[8 * t + q2 + 1];
                accT3[0][sl]     += s[0][us] * (c[t][0] + b20);
                accT3[0][sl + 1] += s[0][us] * (c[t][1] + b21);
                accT3[1][sl]     += s[1][us] * (c[t][2] + b20);
                accT3[1][sl + 1] += s[1][us] * (c[t][3] + b21);
            }
        } else {                                    // block4/5 -> out1
            const bool is5 = (g >= 72);
            const int u0 = is5 ? 2 * (g - 72) : 2 * (g - 64);
            float av[2][2][3];
#pragma unroll
            for (int rr = 0; rr < 2; rr++) {
                const int mm = mA + 8 * rr;
#pragma unroll
                for (int us = 0; us < 2; us++) {
                    const int u = u0 + us;
                    const float xx = x1s[mm * 49 + 3 * u + 0];
                    const float xy = x1s[mm * 49 + 3 * u + 1];
                    const float xz = x1s[mm * 49 + 3 * u + 2];
                    if (!is5) {
                        const float kb = C1IS3 * sh0r[rr];
                        av[rr][us][0] = kb * xx;
                        av[rr][us][1] = kb * xy;
                        av[rr][us][2] = kb * xz;
                    } else {
                        av[rr][us][0] = C1IS6 * (xy * sh1r[rr][2] - xz * sh1r[rr][1]);
                        av[rr][us][1] = C1IS6 * (xz * sh1r[rr][0] - xx * sh1r[rr][2]);
                        av[rr][us][2] = C1IS6 * (xx * sh1r[rr][1] - xy * sh1r[rr][0]);
                    }
                }
            }
#pragma unroll
            for (int t = 0; t < 4; t++) {
                const int us = t >> 1;
                const int sl = 2 * (t & 1);
                const float b20 = b2g[8 * t + q2], b21 = b2g[8 * t + q2 + 1];
                const float D00 = c[t][0] + b20, D01 = c[t][1] + b21;
                const float D10 = c[t][2] + b20, D11 = c[t][3] + b21;
#pragma unroll
                for (int k = 0; k < 3; k++) {
                    accV[0][sl][k]     += av[0][us][k] * D00;
                    accV[0][sl + 1][k] += av[0][us][k] * D01;
                    accV[1][sl][k]     += av[1][us][k] * D10;
                    accV[1][sl + 1][k] += av[1][us][k] * D11;
                }
            }
        }
    }

    // ---- scatter ----
#pragma unroll
    for (int rr = 0; rr < 2; rr++) {
        const int mm = mA + 8 * rr;
        const int src = srcs[mm];
        float* segp = g_seg + (size_t)src * NODE_DIM;
#pragma unroll
        for (int t = 0; t < 4; t++)
#pragma unroll
            for (int b = 0; b < 2; b++)
                atomicAdd(segp + 8 * t + q2 + b, accO[rr][2 * t + b]);
#pragma unroll
        for (int ws = 0; ws < 2; ws++)
#pragma unroll
            for (int b = 0; b < 2; b++) {
                const int wc = 8 * ws + q2 + b;
#pragma unroll
                for (int k = 0; k < 3; k++)
                    atomicAdd(segp + 32 + 3 * wc + k,
                              fmaf(sh1r[rr][k], accT3[rr][2 * ws + b], accV[rr][2 * ws + b][k]));
            }
    }
}

// ---------------- node epilogue ----------------
__global__ void node_kernel(const float* __restrict__ node_attr,
                            const float* __restrict__ mean_shift,
                            const float* __restrict__ aw,
                            const float* __restrict__ ab,
                            float* __restrict__ out) {
    const int warp = (blockIdx.x * blockDim.x + threadIdx.x) >> 5;
    const int lane = threadIdx.x & 31;
    if (warp >= N_NODES) return;
    const unsigned full = 0xFFFFFFFFu;

    const float inv = 1.0f / fmaxf(g_cnt[warp], 1.0f);
    const float* seg = g_seg + (size_t)warp * NODE_DIM;
    const float* na  = node_attr + (size_t)warp * NODE_DIM;

    float o0 = seg[lane] * inv + na[lane];
    float mval = o0;
#pragma unroll
    for (int off = 16; off; off >>= 1) mval += __shfl_xor_sync(full, mval, off);
    mval *= (1.0f / 32.0f);
    const float f0 = o0 - mval * mean_shift[lane];
    float s = f0 * f0;
#pragma unroll
    for (int off = 16; off; off >>= 1) s += __shfl_xor_sync(full, s, off);
    const float sc0 = rsqrtf(s * (1.0f / 32.0f) + EPS_LN) * aw[lane];
    out[(size_t)warp * NODE_DIM + lane] = f0 * sc0 + ab[lane];

    float vx = 0.0f, vy = 0.0f, vz = 0.0f, msv = 0.0f;
    if (lane < 16) {
        vx = seg[32 + 3 * lane + 0] * inv + na[32 + 3 * lane + 0];
        vy = seg[32 + 3 * lane + 1] * inv + na[32 + 3 * lane + 1];
        vz = seg[32 + 3 * lane + 2] * inv + na[32 + 3 * lane + 2];
        msv = mean_shift[32 + lane];
    }
    float mx = vx, my = vy, mz = vz;
#pragma unroll
    for (int off = 16; off; off >>= 1) {
        mx += __shfl_xor_sync(full, mx, off);
        my += __shfl_xor_sync(full, my, off);
        mz += __shfl_xor_sync(full, mz, off);
    }
    mx *= (1.0f / 16.0f); my *= (1.0f / 16.0f); mz *= (1.0f / 16.0f);
    const float fx = vx - mx * msv;
    const float fy = vy - my * msv;
    const float fz = vz - mz * msv;
    float sq = (lane < 16) ? (fx * fx + fy * fy + fz * fz) : 0.0f;
#pragma unroll
    for (int off = 16; off; off >>= 1) sq += __shfl_xor_sync(full, sq, off);
    if (lane < 16) {
        const float sc1 = rsqrtf(sq * (1.0f / 48.0f) + EPS_LN) * aw[32 + lane];
        out[(size_t)warp * NODE_DIM + 32 + 3 * lane + 0] = fx * sc1;
        out[(size_t)warp * NODE_DIM + 32 + 3 * lane + 1] = fy * sc1;
        out[(size_t)warp * NODE_DIM + 32 + 3 * lane + 2] = fz * sc1;
    }
}

// ---------------- launch ----------------
extern "C" void kernel_launch(void* const* d_in, const int* in_sizes, int n_in,
                              void* d_out, int out_size) {
    const float* node_attr  = (const float*)d_in[0];
    const float* edge_attr  = (const float*)d_in[1];
    const float* edge_sh    = (const float*)d_in[2];
    const float* fc_w1      = (const float*)d_in[3];
    const float* fc_b1      = (const float*)d_in[4];
    const float* fc_w2      = (const float*)d_in[5];
    const float* fc_b2      = (const float*)d_in[6];
    const float* mean_shift = (const float*)d_in[7];
    const float* aw         = (const float*)d_in[8];
    const float* ab         = (const float*)d_in[9];
    const int*   edge_index = (const int*)d_in[10];
    float* out = (float*)d_out;

    cudaFuncSetAttribute(gemm1_kernel, cudaFuncAttributeMaxDynamicSharedMemorySize, (int)G1_SMEM);
    cudaFuncSetAttribute(edge_kernel,  cudaFuncAttributeMaxDynamicSharedMemorySize, (int)EDGE_SMEM);

    prep_kernel<<<320, 256>>>(fc_w1, fc_w2);
    gemm1_kernel<<<N_EDGES / 128, 256, G1_SMEM>>>(edge_attr, fc_b1);
    edge_kernel<<<NTILES, 256, EDGE_SMEM>>>(node_attr, edge_sh, fc_b2, edge_index);
    node_kernel<<<(N_NODES * 32 + 255) / 256, 256>>>(node_attr, mean_shift, aw, ab, out);
}

// round 6
// speedup vs baseline: 8.4503x; 1.1716x over previous
#include <cuda_runtime.h>
#include <cuda_fp16.h>
#include <cstdint>
#include <cstddef>

#define N_NODES 20000
#define N_EDGES 160000
#define MUL0 32
#define MUL1 16
#define NODE_DIM 80
#define EDGE_FEAT 128
#define HIDDEN 128
#define W_NUMEL 2560
#define MTILE 128                     // edges per CTA (edge kernel)
#define NTILES (N_EDGES / MTILE)      // 1250
#define NCHUNK 64                     // fc_w2 cols per chunk
#define NCHUNKS (W_NUMEL / NCHUNK)    // 40

#define C0f   0.14433756729740643f
#define C1f   0.21650635094610965f
#define IS3f  0.5773502691896258f
#define IS6f  0.40824829046386296f
#define C0IS3 (C0f * IS3f)
#define C1IS3 (C1f * IS3f)
#define C1IS6 (C1f * IS6f)
#define EPS_LN 1e-5f

// ---------------- device scratch ----------------
__device__ __align__(16) __half g_A[(size_t)N_EDGES * HIDDEN];     // h fp16, [e][k]
__device__ __align__(16) __half g_Bf16[(size_t)W_NUMEL * HIDDEN];  // W2^T fp16 [n][k]
__device__ float g_seg[(size_t)N_NODES * NODE_DIM];
__device__ float g_cnt[N_NODES];

// ---------------- PTX helpers ----------------
__device__ __forceinline__ uint32_t smem_u32(const void* p) {
    uint32_t a;
    asm("{ .reg .u64 t; cvta.to.shared.u64 t, %1; cvt.u32.u64 %0, t; }" : "=r"(a) : "l"(p));
    return a;
}
__device__ __forceinline__ void ldsm_x4(uint32_t* r, uint32_t addr) {
    asm volatile("ldmatrix.sync.aligned.m8n8.x4.shared.b16 {%0,%1,%2,%3}, [%4];"
        : "=r"(r[0]), "=r"(r[1]), "=r"(r[2]), "=r"(r[3]) : "r"(addr));
}
__device__ __forceinline__ void mma_f16(float* c, const uint32_t* a, uint32_t b0, uint32_t b1) {
    asm volatile("mma.sync.aligned.m16n8k16.row.col.f32.f16.f16.f32 "
        "{%0,%1,%2,%3}, {%4,%5,%6,%7}, {%8,%9}, {%0,%1,%2,%3};"
        : "+f"(c[0]), "+f"(c[1]), "+f"(c[2]), "+f"(c[3])
        : "r"(a[0]), "r"(a[1]), "r"(a[2]), "r"(a[3]), "r"(b0), "r"(b1));
}
__device__ __forceinline__ void cp_async16(uint32_t smem_addr, const void* gptr) {
    asm volatile("cp.async.ca.shared.global [%0], [%1], 16;" :: "r"(smem_addr), "l"(gptr));
}
#define CP_COMMIT() asm volatile("cp.async.commit_group;" ::: "memory")
#define CP_WAIT_0() asm volatile("cp.async.wait_group 0;" ::: "memory")

#define ROWB 272

// ---------------- GEMM1 (fp16 2-pass A hi/lo) + embedded prep ----------------
// smem: Ahi fp16[128][272]@0, Alo@34816, W@69632 (34816), b1@104448(512) => 104960
#define G1_AHI 0
#define G1_ALO 34816
#define G1_W   69632
#define G1_B1  104448
#define G1_SMEM 104960

__global__ __launch_bounds__(256, 2)
void gemm1_kernel(const float* __restrict__ edge_attr,
                  const float* __restrict__ fc_w1,
                  const float* __restrict__ fc_b1,
                  const float* __restrict__ fc_w2) {
    extern __shared__ char smc[];
    const uint32_t smb = smem_u32(smc);
    const int tid = threadIdx.x;
    const int w = tid >> 5;
    const int lane = tid & 31;
    const int e0 = blockIdx.x * 128;

    // ---- embedded prep (block-strided slices) ----
    {
        const int gt = blockIdx.x * 256 + tid;
        const int gs = gridDim.x * 256;
        for (int i = gt; i < N_NODES * NODE_DIM; i += gs) g_seg[i] = 0.0f;
        for (int i = gt; i < N_NODES; i += gs) g_cnt[i] = 0.0f;
        for (int i = gt; i < HIDDEN * W_NUMEL; i += gs) {
            const int n = i >> 7, k = i & 127;
            g_Bf16[i] = __float2half_rn(fc_w2[(size_t)k * W_NUMEL + n]);
        }
    }

    // ---- W1 fp32 -> fp16 transposed into SMEM ----
    for (int i = tid; i < HIDDEN * HIDDEN; i += 256) {
        const int k = i >> 7, n = i & 127;       // read fc_w1[k][n] coalesced
        *(__half*)(smc + G1_W + n * ROWB + k * 2) = __float2half_rn(fc_w1[i]);
    }

    // ---- stage A: fp32 -> fp16 hi/lo ----
    const float4* ga = (const float4*)(edge_attr + (size_t)e0 * EDGE_FEAT);
#pragma unroll
    for (int it = 0; it < 16; it++) {
        const int i = tid + it * 256;           // 0..4095 = row(128) x kc4(32)
        const int row = i >> 5, kc4 = i & 31;
        const float4 v = ga[i];
        const __half hx = __float2half_rn(v.x), hy = __float2half_rn(v.y);
        const __half hz = __float2half_rn(v.z), hw = __float2half_rn(v.w);
        const __half lx = __float2half_rn(v.x - __half2float(hx));
        const __half ly = __float2half_rn(v.y - __half2float(hy));
        const __half lz = __float2half_rn(v.z - __half2float(hz));
        const __half lw = __float2half_rn(v.w - __half2float(hw));
        char* dh = smc + G1_AHI + row * ROWB + kc4 * 8;
        char* dl = smc + G1_ALO + row * ROWB + kc4 * 8;
        *(__half2*)(dh)     = __halves2half2(hx, hy);
        *(__half2*)(dh + 4) = __halves2half2(hz, hw);
        *(__half2*)(dl)     = __halves2half2(lx, ly);
        *(__half2*)(dl + 4) = __halves2half2(lz, lw);
    }
    if (tid < 128) ((float*)(smc + G1_B1))[tid] = fc_b1[tid];
    __syncthreads();

    const int q2 = 2 * (lane & 3);
    const int r8 = lane >> 2;
    const int mA = 16 * w + r8;

    const uint32_t aRow = (uint32_t)(16 * w + (lane & 7) + ((lane >> 3) & 1) * 8);
    const uint32_t aK = (uint32_t)(((lane >> 4) & 1) * 16);
    const uint32_t aHiB = smb + G1_AHI + aRow * ROWB + aK;
    const uint32_t aLoB = smb + G1_ALO + aRow * ROWB + aK;
    const uint32_t bRow = (uint32_t)((lane & 7) + ((lane >> 4) & 1) * 8);
    const uint32_t bK = (uint32_t)(((lane >> 3) & 1) * 16);
    const uint32_t wB = smb + G1_W + bRow * ROWB + bK;

    float c[16][4];
#pragma unroll
    for (int t = 0; t < 16; t++)
#pragma unroll
        for (int i = 0; i < 4; i++) c[t][i] = 0.0f;

#pragma unroll
    for (int ks = 0; ks < 8; ks++) {
        uint32_t ah[4], al[4];
        ldsm_x4(ah, aHiB + ks * 32);
        ldsm_x4(al, aLoB + ks * 32);
#pragma unroll
        for (int tp = 0; tp < 8; tp++) {
            uint32_t wf[4];
            ldsm_x4(wf, wB + tp * (16 * ROWB) + ks * 32);
            mma_f16(c[2 * tp],     ah, wf[0], wf[1]);
            mma_f16(c[2 * tp],     al, wf[0], wf[1]);
            mma_f16(c[2 * tp + 1], ah, wf[2], wf[3]);
            mma_f16(c[2 * tp + 1], al, wf[2], wf[3]);
        }
    }

    // bias + relu -> fp16 -> global
    const float* b1s = (const float*)(smc + G1_B1);
#pragma unroll
    for (int t = 0; t < 16; t++) {
        const int col = 8 * t + q2;
        const float bb0 = b1s[col], bb1 = b1s[col + 1];
#pragma unroll
        for (int rr = 0; rr < 2; rr++) {
            const int mm = mA + 8 * rr;
            const float v0 = fmaxf(c[t][2 * rr + 0] + bb0, 0.0f);
            const float v1 = fmaxf(c[t][2 * rr + 1] + bb1, 0.0f);
            *(__half2*)(g_A + (size_t)(e0 + mm) * HIDDEN + col) =
                __halves2half2(__float2half_rn(v0), __float2half_rn(v1));
        }
    }
}

// ---------------- fused fp16 HMMA GEMM2 + tensor product + scatter (MTILE=128) ----------------
// smem: A[128][272]@0 (34816), B 2x[64][272]@34816 (34816),
//       x0s@69632 (16896), x1s@86528 (25088), shs@111616 (2048), srcs@113664 (512) => 114176
#define OFF_A   0
#define OFF_B   34816
#define BBUF    17408
#define OFF_X0  69632
#define OFF_X1  86528
#define OFF_SH  111616
#define OFF_SRC 113664
#define EDGE_SMEM 114176

__global__ __launch_bounds__(256, 2)
void edge_kernel(const float* __restrict__ node_attr,
                 const float* __restrict__ edge_sh,
                 const float* __restrict__ fc_b2,
                 const int*   __restrict__ edge_index) {
    extern __shared__ char smc[];
    const uint32_t smb = smem_u32(smc);
    float* x0s = (float*)(smc + OFF_X0);
    float* x1s = (float*)(smc + OFF_X1);
    float* shs = (float*)(smc + OFF_SH);
    int*  srcs = (int*)(smc + OFF_SRC);

    const int tid  = threadIdx.x;
    const int w    = tid >> 5;          // warp 0..7 -> rows 16w..16w+15
    const int lane = tid & 31;
    const int e0 = blockIdx.x * MTILE;

    // issue B chunk 0 + A tile via cp.async
#pragma unroll
    for (int it = 0; it < 4; it++) {
        const int i = tid + it * 256;       // 0..1023 = row(64) x kc(16)
        const int row = i >> 4, kc = i & 15;
        cp_async16(smb + OFF_B + row * ROWB + kc * 16,
                   g_Bf16 + (size_t)row * HIDDEN + kc * 8);
    }
#pragma unroll
    for (int it = 0; it < 8; it++) {
        const int i = tid + it * 256;       // 0..2047 = row(128) x kc(16)
        const int row = i >> 4, kc = i & 15;
        cp_async16(smb + OFF_A + row * ROWB + kc * 16,
                   g_A + (size_t)(e0 + row) * HIDDEN + kc * 8);
    }
    CP_COMMIT();

    // gather per-edge vectors (one thread per edge)
    if (tid < MTILE) {
        const int eg  = e0 + tid;
        const int src = edge_index[eg];
        const int dst = edge_index[N_EDGES + eg];
        srcs[tid] = src;
        atomicAdd(&g_cnt[src], 1.0f);
        const float4* na = (const float4*)(node_attr + (size_t)dst * NODE_DIM);
#pragma unroll
        for (int q = 0; q < 8; q++) {
            const float4 v = na[q];
            x0s[tid * 33 + 4 * q + 0] = v.x;
            x0s[tid * 33 + 4 * q + 1] = v.y;
            x0s[tid * 33 + 4 * q + 2] = v.z;
            x0s[tid * 33 + 4 * q + 3] = v.w;
        }
#pragma unroll
        for (int q = 0; q < 12; q++) {
            const float4 v = na[8 + q];
            x1s[tid * 49 + 4 * q + 0] = v.x;
            x1s[tid * 49 + 4 * q + 1] = v.y;
            x1s[tid * 49 + 4 * q + 2] = v.z;
            x1s[tid * 49 + 4 * q + 3] = v.w;
        }
        const float4 sh4 = *(const float4*)(edge_sh + (size_t)eg * 4);
        shs[tid * 4 + 0] = sh4.x;
        shs[tid * 4 + 1] = sh4.y;
        shs[tid * 4 + 2] = sh4.z;
        shs[tid * 4 + 3] = sh4.w;
    }

    const int q2 = 2 * (lane & 3);
    const int r8 = lane >> 2;
    const int mA = 16 * w + r8;            // rows mA, mA+8

    const uint32_t aRow = (uint32_t)(16 * w + (lane & 7) + ((lane >> 3) & 1) * 8);
    const uint32_t aK = (uint32_t)(((lane >> 4) & 1) * 16);
    const uint32_t aB = smb + OFF_A + aRow * ROWB + aK;
    const uint32_t bRow = (uint32_t)((lane & 7) + ((lane >> 4) & 1) * 8);
    const uint32_t bK = (uint32_t)(((lane >> 3) & 1) * 16);
    const uint32_t bBase0 = smb + OFF_B + bRow * ROWB + bK;

    float sh0r[2], sh1r[2][3];
#pragma unroll
    for (int rr = 0; rr < 2; rr++) { sh0r[rr] = 0.f; sh1r[rr][0] = sh1r[rr][1] = sh1r[rr][2] = 0.f; }

    float accO[2][8], accT3[2][4], accV[2][4][3];
#pragma unroll
    for (int rr = 0; rr < 2; rr++) {
#pragma unroll
        for (int i = 0; i < 8; i++) accO[rr][i] = 0.0f;
#pragma unroll
        for (int i = 0; i < 4; i++) {
            accT3[rr][i] = 0.0f;
#pragma unroll
            for (int k = 0; k < 3; k++) accV[rr][i][k] = 0.0f;
        }
    }

    bool shLoaded = false;

    for (int j = 0; j < NCHUNKS; j++) {
        CP_WAIT_0();
        __syncthreads();
        if (!shLoaded) {
#pragma unroll
            for (int rr = 0; rr < 2; rr++) {
                const int mm = mA + 8 * rr;
                sh0r[rr] = shs[mm * 4 + 0];
                sh1r[rr][0] = shs[mm * 4 + 1];
                sh1r[rr][1] = shs[mm * 4 + 2];
                sh1r[rr][2] = shs[mm * 4 + 3];
            }
            shLoaded = true;
        }
        // prefetch chunk j+1
        if (j + 1 < NCHUNKS) {
            const uint32_t sb = smb + OFF_B + ((j + 1) & 1) * BBUF;
            const __half* gp0 = g_Bf16 + (size_t)(j + 1) * NCHUNK * HIDDEN;
#pragma unroll
            for (int it = 0; it < 4; it++) {
                const int i = tid + it * 256;
                const int row = i >> 4, kc = i & 15;
                cp_async16(sb + row * ROWB + kc * 16, gp0 + (size_t)row * HIDDEN + kc * 8);
            }
            CP_COMMIT();
        }

        // ---- MMA: rows [16w,16w+16) x all 64 chunk cols, single fp16 pass ----
        const uint32_t bb = bBase0 + (j & 1) * BBUF;
        float c[8][4];
#pragma unroll
        for (int t = 0; t < 8; t++)
#pragma unroll
            for (int i = 0; i < 4; i++) c[t][i] = 0.0f;

#pragma unroll
        for (int ks = 0; ks < 8; ks++) {
            uint32_t ah[4];
            ldsm_x4(ah, aB + ks * 32);
#pragma unroll
            for (int tp = 0; tp < 4; tp++) {
                uint32_t bf[4];
                ldsm_x4(bf, bb + tp * (16 * ROWB) + ks * 32);
                mma_f16(c[2 * tp],     ah, bf[0], bf[1]);
                mma_f16(c[2 * tp + 1], ah, bf[2], bf[3]);
            }
        }

        // ---- epilogue: two 32-col groups g = 2j, 2j+1 ----
#pragma unroll
        for (int gi = 0; gi < 2; gi++) {
            const int g = 2 * j + gi;
            const int t0 = 4 * gi;
            float b2v[4][2];
#pragma unroll
            for (int tt = 0; tt < 4; tt++) {
                const float2 bv = __ldg((const float2*)(fc_b2 + 32 * g + 8 * tt + q2));
                b2v[tt][0] = bv.x; b2v[tt][1] = bv.y;
            }

            if (g < 32) {                               // block1 -> out0 (u = g)
                float s[2];
#pragma unroll
                for (int rr = 0; rr < 2; rr++)
                    s[rr] = C0f * sh0r[rr] * x0s[(mA + 8 * rr) * 33 + g];
#pragma unroll
                for (int tt = 0; tt < 4; tt++) {
                    float* cc = c[t0 + tt];
                    accO[0][2 * tt]     += s[0] * (cc[0] + b2v[tt][0]);
                    accO[0][2 * tt + 1] += s[0] * (cc[1] + b2v[tt][1]);
                    accO[1][2 * tt]     += s[1] * (cc[2] + b2v[tt][0]);
                    accO[1][2 * tt + 1] += s[1] * (cc[3] + b2v[tt][1]);
                }
            } else if (g < 48) {                        // block2 -> out0 (u = g-32)
                const int u = g - 32;
                float s[2];
#pragma unroll
                for (int rr = 0; rr < 2; rr++) {
                    const int mm = mA + 8 * rr;
                    s[rr] = C0IS3 * (x1s[mm * 49 + 3 * u] * sh1r[rr][0]
                                   + x1s[mm * 49 + 3 * u + 1] * sh1r[rr][1]
                                   + x1s[mm * 49 + 3 * u + 2] * sh1r[rr][2]);
                }
#pragma unroll
                for (int tt = 0; tt < 4; tt++) {
                    float* cc = c[t0 + tt];
                    accO[0][2 * tt]     += s[0] * (cc[0] + b2v[tt][0]);
                    accO[0][2 * tt + 1] += s[0] * (cc[1] + b2v[tt][1]);
                    accO[1][2 * tt]     += s[1] * (cc[2] + b2v[tt][0]);
                    accO[1][2 * tt + 1] += s[1] * (cc[3] + b2v[tt][1]);
                }
            } else if (g < 64) {                        // block3 -> t3
                const int u0 = 2 * (g - 48);
                float s[2][2];
#pragma unroll
                for (int rr = 0; rr < 2; rr++) {
                    const int mm = mA + 8 * rr;
                    s[rr][0] = C1IS3 * x0s[mm * 33 + u0];
                    s[rr][1] = C1IS3 * x0s[mm * 33 + u0 + 1];
                }
#pragma unroll
                for (int tt = 0; tt < 4; tt++) {
                    const int us = tt >> 1;
                    const int sl = 2 * (tt & 1);
                    float* cc = c[t0 + tt];
                    accT3[0][sl]     += s[0][us] * (cc[0] + b2v[tt][0]);
                    accT3[0][sl + 1] += s[0][us] * (cc[1] + b2v[tt][1]);
                    accT3[1][sl]     += s[1][us] * (cc[2] + b2v[tt][0]);
                    accT3[1][sl + 1] += s[1][us] * (cc[3] + b2v[tt][1]);
                }
            } else {                                    // block4/5 -> out1
                const bool is5 = (g >= 72);
                const int u0 = is5 ? 2 * (g - 72) : 2 * (g - 64);
                float av[2][2][3];
#pragma unroll
                for (int rr = 0; rr < 2; rr++) {
                    const int mm = mA + 8 * rr;
#pragma unroll
                    for (int us = 0; us < 2; us++) {
                        const int u = u0 + us;
                        const float xx = x1s[mm * 49 + 3 * u + 0];
                        const float xy = x1s[mm * 49 + 3 * u + 1];
                        const float xz = x1s[mm * 49 + 3 * u + 2];
                        if (!is5) {
                            const float kb = C1IS3 * sh0r[rr];
                            av[rr][us][0] = kb * xx;
                            av[rr][us][1] = kb * xy;
                            av[rr][us][2] = kb * xz;
                        } else {
                            av[rr][us][0] = C1IS6 * (xy * sh1r[rr][2] - xz * sh1r[rr][1]);
                            av[rr][us][1] = C1IS6 * (xz * sh1r[rr][0] - xx * sh1r[rr][2]);
                            av[rr][us][2] = C1IS6 * (xx * sh1r[rr][1] - xy * sh1r[rr][0]);
                        }
                    }
                }
#pragma unroll
                for (int tt = 0; tt < 4; tt++) {
                    const int us = tt >> 1;
                    const int sl = 2 * (tt & 1);
                    float* cc = c[t0 + tt];
                    const float D00 = cc[0] + b2v[tt][0], D01 = cc[1] + b2v[tt][1];
                    const float D10 = cc[2] + b2v[tt][0], D11 = cc[3] + b2v[tt][1];
#pragma unroll
                    for (int k = 0; k < 3; k++) {
                        accV[0][sl][k]     += av[0][us][k] * D00;
                        accV[0][sl + 1][k] += av[0][us][k] * D01;
                        accV[1][sl][k]     += av[1][us][k] * D10;
                        accV[1][sl + 1][k] += av[1][us][k] * D11;
                    }
                }
            }
        }
    }

    // ---- scatter ----
#pragma unroll
    for (int rr = 0; rr < 2; rr++) {
        const int mm = mA + 8 * rr;
        const int src = srcs[mm];
        float* segp = g_seg + (size_t)src * NODE_DIM;
#pragma unroll
        for (int t = 0; t < 4; t++)
#pragma unroll
            for (int b = 0; b < 2; b++)
                atomicAdd(segp + 8 * t + q2 + b, accO[rr][2 * t + b]);
#pragma unroll
        for (int ws = 0; ws < 2; ws++)
#pragma unroll
            for (int b = 0; b < 2; b++) {
                const int wc = 8 * ws + q2 + b;
#pragma unroll
                for (int k = 0; k < 3; k++)
                    atomicAdd(segp + 32 + 3 * wc + k,
                              fmaf(sh1r[rr][k], accT3[rr][2 * ws + b], accV[rr][2 * ws + b][k]));
            }
    }
}

// ---------------- node epilogue ----------------
__global__ void node_kernel(const float* __restrict__ node_attr,
                            const float* __restrict__ mean_shift,
                            const float* __restrict__ aw,
                            const float* __restrict__ ab,
                            float* __restrict__ out) {
    const int warp = (blockIdx.x * blockDim.x + threadIdx.x) >> 5;
    const int lane = threadIdx.x & 31;
    if (warp >= N_NODES) return;
    const unsigned full = 0xFFFFFFFFu;

    const float inv = 1.0f / fmaxf(g_cnt[warp], 1.0f);
    const float* seg = g_seg + (size_t)warp * NODE_DIM;
    const float* na  = node_attr + (size_t)warp * NODE_DIM;

    float o0 = seg[lane] * inv + na[lane];
    float mval = o0;
#pragma unroll
    for (int off = 16; off; off >>= 1) mval += __shfl_xor_sync(full, mval, off);
    mval *= (1.0f / 32.0f);
    const float f0 = o0 - mval * mean_shift[lane];
    float s = f0 * f0;
#pragma unroll
    for (int off = 16; off; off >>= 1) s += __shfl_xor_sync(full, s, off);
    const float sc0 = rsqrtf(s * (1.0f / 32.0f) + EPS_LN) * aw[lane];
    out[(size_t)warp * NODE_DIM + lane] = f0 * sc0 + ab[lane];

    float vx = 0.0f, vy = 0.0f, vz = 0.0f, msv = 0.0f;
    if (lane < 16) {
        vx = seg[32 + 3 * lane + 0] * inv + na[32 + 3 * lane + 0];
        vy = seg[32 + 3 * lane + 1] * inv + na[32 + 3 * lane + 1];
        vz = seg[32 + 3 * lane + 2] * inv + na[32 + 3 * lane + 2];
        msv = mean_shift[32 + lane];
    }
    float mx = vx, my = vy, mz = vz;
#pragma unroll
    for (int off = 16; off; off >>= 1) {
        mx += __shfl_xor_sync(full, mx, off);
        my += __shfl_xor_sync(full, my, off);
        mz += __shfl_xor_sync(full, mz, off);
    }
    mx *= (1.0f / 16.0f); my *= (1.0f / 16.0f); mz *= (1.0f / 16.0f);
    const float fx = vx - mx * msv;
    const float fy = vy - my * msv;
    const float fz = vz - mz * msv;
    float sq = (lane < 16) ? (fx * fx + fy * fy + fz * fz) : 0.0f;
#pragma unroll
    for (int off = 16; off; off >>= 1) sq += __shfl_xor_sync(full, sq, off);
    if (lane < 16) {
        const float sc1 = rsqrtf(sq * (1.0f / 48.0f) + EPS_LN) * aw[32 + lane];
        out[(size_t)warp * NODE_DIM + 32 + 3 * lane + 0] = fx * sc1;
        out[(size_t)warp * NODE_DIM + 32 + 3 * lane + 1] = fy * sc1;
        out[(size_t)warp * NODE_DIM + 32 + 3 * lane + 2] = fz * sc1;
    }
}

// ---------------- launch ----------------
extern "C" void kernel_launch(void* const* d_in, const int* in_sizes, int n_in,
                              void* d_out, int out_size) {
    const float* node_attr  = (const float*)d_in[0];
    const float* edge_attr  = (const float*)d_in[1];
    const float* edge_sh    = (const float*)d_in[2];
    const float* fc_w1      = (const float*)d_in[3];
    const float* fc_b1      = (const float*)d_in[4];
    const float* fc_w2      = (const float*)d_in[5];
    const float* fc_b2      = (const float*)d_in[6];
    const float* mean_shift = (const float*)d_in[7];
    const float* aw         = (const float*)d_in[8];
    const float* ab         = (const float*)d_in[9];
    const int*   edge_index = (const int*)d_in[10];
    float* out = (float*)d_out;

    cudaFuncSetAttribute(gemm1_kernel, cudaFuncAttributeMaxDynamicSharedMemorySize, (int)G1_SMEM);
    cudaFuncSetAttribute(edge_kernel,  cudaFuncAttributeMaxDynamicSharedMemorySize, (int)EDGE_SMEM);

    gemm1_kernel<<<N_EDGES / 128, 256, G1_SMEM>>>(edge_attr, fc_w1, fc_b1, fc_w2);
    edge_kernel<<<NTILES, 256, EDGE_SMEM>>>(node_attr, edge_sh, fc_b2, edge_index);
    node_kernel<<<(N_NODES * 32 + 255) / 256, 256>>>(node_attr, mean_shift, aw, ab, out);
}